// round 6
// baseline (speedup 1.0000x reference)
#include <cuda_runtime.h>
#include <cuda_fp16.h>
#include <cstdint>

#define Bsz 4
#define Seq 2048
#define Dm  1024
#define Hn  16
#define Hd  64
#define Mrows (Bsz*Seq)   // 8192

// Scratch (allocation-free rule: __device__ globals)
__device__ float g_q[Bsz*Hn*Seq*Hd];     // [B,H,S,HD]
__device__ float g_k[Bsz*Hn*Seq*Hd];
__device__ float g_v[Bsz*Hn*Seq*Hd];
__device__ float g_att[Bsz*Seq*Dm];      // [B,S,D] (D = h*64+hd)

// ===========================================================================
// Common PTX helpers
// ===========================================================================
__device__ __forceinline__ uint32_t smem_u32(const void* p) {
    uint32_t a;
    asm("{ .reg .u64 t; cvta.to.shared.u64 t, %1; cvt.u32.u64 %0, t; }"
        : "=r"(a) : "l"(p));
    return a;
}

#define CP16(dst, src) \
    asm volatile("cp.async.cg.shared.global [%0], [%1], 16;" :: "r"(dst), "l"(src))
#define CP_COMMIT()  asm volatile("cp.async.commit_group;" ::: "memory")
#define CP_WAIT1()   asm volatile("cp.async.wait_group 1;" ::: "memory")
#define CP_WAIT0()   asm volatile("cp.async.wait_group 0;" ::: "memory")

__device__ __forceinline__ uint32_t f2tf32(float x) {
    uint32_t r;
    asm("cvt.rna.tf32.f32 %0, %1;" : "=r"(r) : "f"(x));
    return r;
}

__device__ __forceinline__ void mma_tf32_16x8x8(float c[4], const uint32_t a[4],
                                                uint32_t b0, uint32_t b1) {
    asm volatile(
        "mma.sync.aligned.m16n8k8.row.col.f32.tf32.tf32.f32 "
        "{%0,%1,%2,%3}, {%4,%5,%6,%7}, {%8,%9}, {%0,%1,%2,%3};"
        : "+f"(c[0]), "+f"(c[1]), "+f"(c[2]), "+f"(c[3])
        : "r"(a[0]), "r"(a[1]), "r"(a[2]), "r"(a[3]), "r"(b0), "r"(b1));
}

__device__ __forceinline__ void mma_f16_16x8x16(float c[4], const uint32_t a[4],
                                                uint32_t b0, uint32_t b1) {
    asm volatile(
        "mma.sync.aligned.m16n8k16.row.col.f32.f16.f16.f32 "
        "{%0,%1,%2,%3}, {%4,%5,%6,%7}, {%8,%9}, {%0,%1,%2,%3};"
        : "+f"(c[0]), "+f"(c[1]), "+f"(c[2]), "+f"(c[3])
        : "r"(a[0]), "r"(a[1]), "r"(a[2]), "r"(a[3]), "r"(b0), "r"(b1));
}

// Split a pair of fp32 into packed half2 hi + half2 lo (hi+lo ≈ 22-bit value)
__device__ __forceinline__ void split_pair(float x, float y,
                                           uint32_t& hi, uint32_t& lo) {
    __half2 h = __floats2half2_rn(x, y);
    float2  hf = __half22float2(h);
    __half2 l = __floats2half2_rn(x - hf.x, y - hf.y);
    hi = *(uint32_t*)&h;
    lo = *(uint32_t*)&l;
}

// ===========================================================================
// 3xFP16 mma.sync GEMM:  C[128x128] tile of X[M,K] @ W[N,K]^T, K=1024
// 8 warps = 2(M) x 4(N); per warp 64x32; m16n8k16 fragments (hi/lo split).
// Double-buffered cp.async K-stages of 32.
// ===========================================================================
#define KT   32
#define PAD  40                      // floats per smem row (conflict-free f2 LDS)
#define STAGE_F (128*PAD)            // floats per operand stage
#define GEMM_SMEM_BYTES (4*STAGE_F*4)  // A0,B0,A1,B1 = 81920 B

__device__ __forceinline__ void gemm_mma_tile(const float* __restrict__ X,
                                              const float* __restrict__ W,
                                              int row0, int col0,
                                              float acc[4][4][4])
{
    extern __shared__ float sm[];
    const int tid  = threadIdx.x;
    const int wid  = tid >> 5, lane = tid & 31;
    const int warpM = wid >> 2, warpN = wid & 3;
    const int quad = lane >> 2, tq = lane & 3;

    uint32_t dA[4], dB[4];
    const float* sA[4];
    const float* sB[4];
    const uint32_t smb = smem_u32(sm);
    #pragma unroll
    for (int it = 0; it < 4; it++) {
        int id = it * 256 + tid;
        int r  = id >> 3;
        int c  = id & 7;
        dA[it] = smb + (uint32_t)(r * PAD + c * 4) * 4u;
        dB[it] = dA[it] + STAGE_F * 4u;
        sA[it] = X + (size_t)(row0 + r) * Dm + c * 4;
        sB[it] = W + (size_t)(col0 + r) * Dm + c * 4;
    }
    const uint32_t stageOff = 2u * STAGE_F * 4u;

    const float* As = sm;
    const float* Bs = sm + STAGE_F;
    const int aRow0 = warpM * 64 + quad;
    const int bRow0 = warpN * 32 + quad;

    #pragma unroll
    for (int it = 0; it < 4; it++) { CP16(dA[it], sA[it]); CP16(dB[it], sB[it]); }
    CP_COMMIT();

    const int NST = Dm / KT;
    for (int s = 0; s < NST; s++) {
        const int cur = s & 1;
        if (s + 1 < NST) {
            const uint32_t bo = (uint32_t)((s + 1) & 1) * stageOff;
            const int ko = (s + 1) * KT;
            #pragma unroll
            for (int it = 0; it < 4; it++) {
                CP16(dA[it] + bo, sA[it] + ko);
                CP16(dB[it] + bo, sB[it] + ko);
            }
            CP_COMMIT();
            CP_WAIT1();
        } else {
            CP_WAIT0();
        }
        __syncthreads();

        const float* Ab = As + cur * 2 * STAGE_F;
        const float* Bb = Bs + cur * 2 * STAGE_F;

        #pragma unroll
        for (int kk = 0; kk < 2; kk++) {
            const int k0 = kk * 16 + 2 * tq;
            uint32_t ah[4][4], al[4][4], bh[4][2], bl[4][2];
            #pragma unroll
            for (int mi = 0; mi < 4; mi++) {
                const float* p = Ab + (aRow0 + mi * 16) * PAD + k0;
                float2 v0 = *(const float2*)(p);
                float2 v1 = *(const float2*)(p + 8 * PAD);
                float2 v2 = *(const float2*)(p + 8);
                float2 v3 = *(const float2*)(p + 8 * PAD + 8);
                split_pair(v0.x, v0.y, ah[mi][0], al[mi][0]);
                split_pair(v1.x, v1.y, ah[mi][1], al[mi][1]);
                split_pair(v2.x, v2.y, ah[mi][2], al[mi][2]);
                split_pair(v3.x, v3.y, ah[mi][3], al[mi][3]);
            }
            #pragma unroll
            for (int ni = 0; ni < 4; ni++) {
                const float* p = Bb + (bRow0 + ni * 8) * PAD + k0;
                float2 v0 = *(const float2*)(p);
                float2 v1 = *(const float2*)(p + 8);
                split_pair(v0.x, v0.y, bh[ni][0], bl[ni][0]);
                split_pair(v1.x, v1.y, bh[ni][1], bl[ni][1]);
            }
            #pragma unroll
            for (int mi = 0; mi < 4; mi++)
                #pragma unroll
                for (int ni = 0; ni < 4; ni++) {
                    mma_f16_16x8x16(acc[mi][ni], al[mi], bh[ni][0], bh[ni][1]);
                    mma_f16_16x8x16(acc[mi][ni], ah[mi], bl[ni][0], bl[ni][1]);
                    mma_f16_16x8x16(acc[mi][ni], ah[mi], bh[ni][0], bh[ni][1]);
                }
        }
        __syncthreads();
    }
}

__global__ __launch_bounds__(256)
void qkv_mma(const float* __restrict__ X,
             const float* __restrict__ Wq, const float* __restrict__ bq,
             const float* __restrict__ Wk, const float* __restrict__ bk,
             const float* __restrict__ Wv, const float* __restrict__ bv)
{
    const float *W, *bias;
    float* out;
    if (blockIdx.z == 0)      { W = Wq; bias = bq; out = g_q; }
    else if (blockIdx.z == 1) { W = Wk; bias = bk; out = g_k; }
    else                      { W = Wv; bias = bv; out = g_v; }

    float acc[4][4][4];
    #pragma unroll
    for (int mi = 0; mi < 4; mi++)
        #pragma unroll
        for (int ni = 0; ni < 4; ni++)
            #pragma unroll
            for (int j = 0; j < 4; j++) acc[mi][ni][j] = 0.f;

    const int row0 = blockIdx.y * 128;
    const int col0 = blockIdx.x * 128;
    gemm_mma_tile(X, W, row0, col0, acc);

    const int tid  = threadIdx.x;
    const int wid  = tid >> 5, lane = tid & 31;
    const int warpM = wid >> 2, warpN = wid & 3;
    const int quad = lane >> 2, tq = lane & 3;

    #pragma unroll
    for (int mi = 0; mi < 4; mi++) {
        #pragma unroll
        for (int half = 0; half < 2; half++) {
            const int r = row0 + warpM * 64 + mi * 16 + quad + half * 8;
            const int b = r >> 11;
            const int sq = r & 2047;
            #pragma unroll
            for (int ni = 0; ni < 4; ni++) {
                const int c  = col0 + warpN * 32 + ni * 8 + 2 * tq;
                const int h  = c >> 6;
                const int hd = c & 63;
                float2 bb = *(const float2*)&bias[c];
                float2 v;
                v.x = acc[mi][ni][half * 2 + 0] + bb.x;
                v.y = acc[mi][ni][half * 2 + 1] + bb.y;
                *(float2*)(out + (((size_t)(b * Hn + h) * Seq + sq) * Hd + hd)) = v;
            }
        }
    }
}

__global__ __launch_bounds__(256)
void proj_mma(const float* __restrict__ Wo, const float* __restrict__ bo,
              const float* __restrict__ comp, float* __restrict__ out)
{
    float acc[4][4][4];
    #pragma unroll
    for (int mi = 0; mi < 4; mi++)
        #pragma unroll
        for (int ni = 0; ni < 4; ni++)
            #pragma unroll
            for (int j = 0; j < 4; j++) acc[mi][ni][j] = 0.f;

    const int row0 = blockIdx.y * 128;
    const int col0 = blockIdx.x * 128;
    gemm_mma_tile(g_att, Wo, row0, col0, acc);

    const int tid  = threadIdx.x;
    const int wid  = tid >> 5, lane = tid & 31;
    const int warpM = wid >> 2, warpN = wid & 3;
    const int quad = lane >> 2, tq = lane & 3;

    #pragma unroll
    for (int mi = 0; mi < 4; mi++) {
        #pragma unroll
        for (int half = 0; half < 2; half++) {
            const int r = row0 + warpM * 64 + mi * 16 + quad + half * 8;
            #pragma unroll
            for (int ni = 0; ni < 4; ni++) {
                const int c = col0 + warpN * 32 + ni * 8 + 2 * tq;
                float2 bb = *(const float2*)&bo[c];
                float2 cc = *(const float2*)&comp[c];
                float2 v;
                v.x = acc[mi][ni][half * 2 + 0] + bb.x + cc.x;
                v.y = acc[mi][ni][half * 2 + 1] + bb.y + cc.y;
                *(float2*)(out + (size_t)r * Dm + c) = v;
            }
        }
    }
}

// ===========================================================================
// Flash attention with 3xTF32 mma (proven R5). BM=BN=64, 4 warps.
// ===========================================================================
#define PQ   68
#define PVV  72
#define QS_F   (64*PQ)
#define VS_F   (64*PVV)
#define FLASH_SMEM_BYTES ((QS_F*3 + VS_F*2)*4)   // 89088

__global__ __launch_bounds__(128)
void flash_mma()
{
    const int qt = blockIdx.x;
    const int bh = blockIdx.y;

    const float* Qg = g_q + (size_t)bh * Seq * Hd;
    const float* Kg = g_k + (size_t)bh * Seq * Hd;
    const float* Vg = g_v + (size_t)bh * Seq * Hd;

    extern __shared__ float fs[];
    float* Qs  = fs;
    float* Ksb[2] = { fs + QS_F, fs + 2*QS_F };
    float* Vsb[2] = { fs + 3*QS_F, fs + 3*QS_F + VS_F };

    const int tid  = threadIdx.x;
    const int wid  = tid >> 5, lane = tid & 31;
    const int quad = lane >> 2, tq = lane & 3;
    const int r0   = wid * 16;

    int crow[8], cseg[8];
    #pragma unroll
    for (int i = 0; i < 8; i++) {
        int id = i * 128 + tid;
        crow[i] = id >> 4;
        cseg[i] = id & 15;
    }
    const uint32_t qsb = smem_u32(Qs);
    const uint32_t ks0 = smem_u32(Ksb[0]), ks1 = smem_u32(Ksb[1]);
    const uint32_t vs0 = smem_u32(Vsb[0]), vs1 = smem_u32(Vsb[1]);

    #pragma unroll
    for (int i = 0; i < 8; i++) {
        CP16(qsb + (uint32_t)(crow[i]*PQ + cseg[i]*4)*4u,
             Qg + (size_t)(qt*64 + crow[i]) * Hd + cseg[i]*4);
        CP16(ks0 + (uint32_t)(crow[i]*PQ + cseg[i]*4)*4u,
             Kg + (size_t)(crow[i]) * Hd + cseg[i]*4);
        CP16(vs0 + (uint32_t)(crow[i]*PVV + cseg[i]*4)*4u,
             Vg + (size_t)(crow[i]) * Hd + cseg[i]*4);
    }
    CP_COMMIT();
    CP_WAIT0();
    __syncthreads();

    uint32_t qhi[8][4], qlo[8][4];
    #pragma unroll
    for (int kk = 0; kk < 8; kk++) {
        const int k0 = kk * 8 + tq;
        float v0 = Qs[(r0 + quad)     * PQ + k0]     * 0.125f;
        float v1 = Qs[(r0 + quad + 8) * PQ + k0]     * 0.125f;
        float v2 = Qs[(r0 + quad)     * PQ + k0 + 4] * 0.125f;
        float v3 = Qs[(r0 + quad + 8) * PQ + k0 + 4] * 0.125f;
        qhi[kk][0] = f2tf32(v0); qlo[kk][0] = f2tf32(v0 - __uint_as_float(qhi[kk][0]));
        qhi[kk][1] = f2tf32(v1); qlo[kk][1] = f2tf32(v1 - __uint_as_float(qhi[kk][1]));
        qhi[kk][2] = f2tf32(v2); qlo[kk][2] = f2tf32(v2 - __uint_as_float(qhi[kk][2]));
        qhi[kk][3] = f2tf32(v3); qlo[kk][3] = f2tf32(v3 - __uint_as_float(qhi[kk][3]));
    }
    float* Ps = Qs;

    float m_i[2] = { -1e30f, -1e30f };
    float l_i[2] = { 0.f, 0.f };
    float oacc[8][4];
    #pragma unroll
    for (int ni = 0; ni < 8; ni++)
        #pragma unroll
        for (int j = 0; j < 4; j++) oacc[ni][j] = 0.f;

    for (int jt = 0; jt <= qt; jt++) {
        __syncthreads();

        const int cur = jt & 1;
        if (jt + 1 <= qt) {
            const uint32_t kd = (jt + 1) & 1 ? ks1 : ks0;
            const uint32_t vd = (jt + 1) & 1 ? vs1 : vs0;
            const size_t roff = (size_t)((jt + 1) * 64);
            #pragma unroll
            for (int i = 0; i < 8; i++) {
                CP16(kd + (uint32_t)(crow[i]*PQ + cseg[i]*4)*4u,
                     Kg + (roff + crow[i]) * Hd + cseg[i]*4);
                CP16(vd + (uint32_t)(crow[i]*PVV + cseg[i]*4)*4u,
                     Vg + (roff + crow[i]) * Hd + cseg[i]*4);
            }
            CP_COMMIT();
            CP_WAIT1();
        } else {
            CP_WAIT0();
        }
        __syncthreads();

        const float* Ks = Ksb[cur];
        const float* Vs = Vsb[cur];

        float sacc[8][4];
        #pragma unroll
        for (int ni = 0; ni < 8; ni++)
            #pragma unroll
            for (int j = 0; j < 4; j++) sacc[ni][j] = 0.f;

        #pragma unroll
        for (int ni = 0; ni < 8; ni++) {
            const float* kb = Ks + (ni * 8 + quad) * PQ;
            #pragma unroll
            for (int kk = 0; kk < 8; kk++) {
                const int k0 = kk * 8 + tq;
                float v0 = kb[k0], v1 = kb[k0 + 4];
                uint32_t bh0 = f2tf32(v0), bl0 = f2tf32(v0 - __uint_as_float(bh0));
                uint32_t bh1 = f2tf32(v1), bl1 = f2tf32(v1 - __uint_as_float(bh1));
                mma_tf32_16x8x8(sacc[ni], qlo[kk], bh0, bh1);
                mma_tf32_16x8x8(sacc[ni], qhi[kk], bl0, bl1);
                mma_tf32_16x8x8(sacc[ni], qhi[kk], bh0, bh1);
            }
        }

        if (jt == qt) {
            const int ib0 = r0 + quad;
            #pragma unroll
            for (int ni = 0; ni < 8; ni++) {
                const int jb = ni * 8 + 2 * tq;
                if (jb     > ib0)     sacc[ni][0] = -1e30f;
                if (jb + 1 > ib0)     sacc[ni][1] = -1e30f;
                if (jb     > ib0 + 8) sacc[ni][2] = -1e30f;
                if (jb + 1 > ib0 + 8) sacc[ni][3] = -1e30f;
            }
        }

        float mloc0 = -1e30f, mloc1 = -1e30f;
        #pragma unroll
        for (int ni = 0; ni < 8; ni++) {
            mloc0 = fmaxf(mloc0, fmaxf(sacc[ni][0], sacc[ni][1]));
            mloc1 = fmaxf(mloc1, fmaxf(sacc[ni][2], sacc[ni][3]));
        }
        #pragma unroll
        for (int off = 1; off < 4; off <<= 1) {
            mloc0 = fmaxf(mloc0, __shfl_xor_sync(0xffffffffu, mloc0, off));
            mloc1 = fmaxf(mloc1, __shfl_xor_sync(0xffffffffu, mloc1, off));
        }
        const float mnew0 = fmaxf(m_i[0], mloc0);
        const float mnew1 = fmaxf(m_i[1], mloc1);
        const float al0 = __expf(m_i[0] - mnew0);
        const float al1 = __expf(m_i[1] - mnew1);
        float ps0 = 0.f, ps1 = 0.f;
        #pragma unroll
        for (int ni = 0; ni < 8; ni++) {
            sacc[ni][0] = __expf(sacc[ni][0] - mnew0);
            sacc[ni][1] = __expf(sacc[ni][1] - mnew0);
            sacc[ni][2] = __expf(sacc[ni][2] - mnew1);
            sacc[ni][3] = __expf(sacc[ni][3] - mnew1);
            ps0 += sacc[ni][0] + sacc[ni][1];
            ps1 += sacc[ni][2] + sacc[ni][3];
        }
        #pragma unroll
        for (int off = 1; off < 4; off <<= 1) {
            ps0 += __shfl_xor_sync(0xffffffffu, ps0, off);
            ps1 += __shfl_xor_sync(0xffffffffu, ps1, off);
        }
        l_i[0] = l_i[0] * al0 + ps0;  m_i[0] = mnew0;
        l_i[1] = l_i[1] * al1 + ps1;  m_i[1] = mnew1;
        #pragma unroll
        for (int ni = 0; ni < 8; ni++) {
            oacc[ni][0] *= al0; oacc[ni][1] *= al0;
            oacc[ni][2] *= al1; oacc[ni][3] *= al1;
        }

        #pragma unroll
        for (int ni = 0; ni < 8; ni++) {
            *(float2*)&Ps[(r0 + quad)     * PQ + ni * 8 + 2 * tq] =
                make_float2(sacc[ni][0], sacc[ni][1]);
            *(float2*)&Ps[(r0 + quad + 8) * PQ + ni * 8 + 2 * tq] =
                make_float2(sacc[ni][2], sacc[ni][3]);
        }
        __syncwarp();

        #pragma unroll
        for (int kk = 0; kk < 8; kk++) {
            const int k0 = kk * 8 + tq;
            float p0 = Ps[(r0 + quad)     * PQ + k0];
            float p1 = Ps[(r0 + quad + 8) * PQ + k0];
            float p2 = Ps[(r0 + quad)     * PQ + k0 + 4];
            float p3 = Ps[(r0 + quad + 8) * PQ + k0 + 4];
            uint32_t ph[4], pl[4];
            ph[0] = f2tf32(p0); pl[0] = f2tf32(p0 - __uint_as_float(ph[0]));
            ph[1] = f2tf32(p1); pl[1] = f2tf32(p1 - __uint_as_float(ph[1]));
            ph[2] = f2tf32(p2); pl[2] = f2tf32(p2 - __uint_as_float(ph[2]));
            ph[3] = f2tf32(p3); pl[3] = f2tf32(p3 - __uint_as_float(ph[3]));
            const float* vb0 = Vs + (kk * 8 + tq) * PVV;
            const float* vb1 = Vs + (kk * 8 + tq + 4) * PVV;
            #pragma unroll
            for (int ni = 0; ni < 8; ni++) {
                float v0 = vb0[ni * 8 + quad];
                float v1 = vb1[ni * 8 + quad];
                uint32_t bh0 = f2tf32(v0), bl0 = f2tf32(v0 - __uint_as_float(bh0));
                uint32_t bh1 = f2tf32(v1), bl1 = f2tf32(v1 - __uint_as_float(bh1));
                mma_tf32_16x8x8(oacc[ni], pl, bh0, bh1);
                mma_tf32_16x8x8(oacc[ni], ph, bl0, bl1);
                mma_tf32_16x8x8(oacc[ni], ph, bh0, bh1);
            }
        }
        __syncwarp();
    }

    const int bidx = bh >> 4, h = bh & 15;
    #pragma unroll
    for (int half = 0; half < 2; half++) {
        const float inv = 1.0f / l_i[half];
        const int s = qt * 64 + r0 + quad + half * 8;
        float* dst = g_att + (((size_t)bidx * Seq + s) * Hn + h) * Hd;
        #pragma unroll
        for (int ni = 0; ni < 8; ni++) {
            float2 v = make_float2(oacc[ni][half * 2 + 0] * inv,
                                   oacc[ni][half * 2 + 1] * inv);
            *(float2*)(dst + ni * 8 + 2 * tq) = v;
        }
    }
}

// ---------------------------------------------------------------------------
extern "C" void kernel_launch(void* const* d_in, const int* in_sizes, int n_in,
                              void* d_out, int out_size)
{
    (void)in_sizes; (void)n_in; (void)out_size;
    const float* X    = (const float*)d_in[0];
    const float* Wq   = (const float*)d_in[1];
    const float* bq   = (const float*)d_in[2];
    const float* Wk   = (const float*)d_in[3];
    const float* bk   = (const float*)d_in[4];
    const float* Wv   = (const float*)d_in[5];
    const float* bv   = (const float*)d_in[6];
    const float* Wo   = (const float*)d_in[7];
    const float* bo   = (const float*)d_in[8];
    const float* comp = (const float*)d_in[9];
    float* out = (float*)d_out;

    cudaFuncSetAttribute(qkv_mma,   cudaFuncAttributeMaxDynamicSharedMemorySize, GEMM_SMEM_BYTES);
    cudaFuncSetAttribute(proj_mma,  cudaFuncAttributeMaxDynamicSharedMemorySize, GEMM_SMEM_BYTES);
    cudaFuncSetAttribute(flash_mma, cudaFuncAttributeMaxDynamicSharedMemorySize, FLASH_SMEM_BYTES);

    dim3 gQKV(Dm/128, Mrows/128, 3);     // (8, 64, 3)
    qkv_mma<<<gQKV, 256, GEMM_SMEM_BYTES>>>(X, Wq, bq, Wk, bk, Wv, bv);

    dim3 gFA(Seq/64, Bsz*Hn);            // (32, 64)
    flash_mma<<<gFA, 128, FLASH_SMEM_BYTES>>>();

    dim3 gP(Dm/128, Mrows/128);          // (8, 64)
    proj_mma<<<gP, 256, GEMM_SMEM_BYTES>>>(Wo, bo, comp, out);
}

// round 7
// speedup vs baseline: 1.1361x; 1.1361x over previous
#include <cuda_runtime.h>
#include <cstdint>

#define Bsz 4
#define Seq 2048
#define Dm  1024
#define Hn  16
#define Hd  64
#define Mrows (Bsz*Seq)   // 8192

// Scratch (allocation-free rule: __device__ globals)
__device__ float g_q[Bsz*Hn*Seq*Hd];     // [B,H,S,HD]
__device__ float g_k[Bsz*Hn*Seq*Hd];
__device__ float g_v[Bsz*Hn*Seq*Hd];
__device__ float g_att[Bsz*Seq*Dm];      // [B,S,D] (D = h*64+hd)

// ===========================================================================
// Common PTX helpers
// ===========================================================================
__device__ __forceinline__ uint32_t smem_u32(const void* p) {
    uint32_t a;
    asm("{ .reg .u64 t; cvta.to.shared.u64 t, %1; cvt.u32.u64 %0, t; }"
        : "=r"(a) : "l"(p));
    return a;
}

#define CP16(dst, src) \
    asm volatile("cp.async.cg.shared.global [%0], [%1], 16;" :: "r"(dst), "l"(src))
#define CP_COMMIT()  asm volatile("cp.async.commit_group;" ::: "memory")
#define CP_WAIT1()   asm volatile("cp.async.wait_group 1;" ::: "memory")
#define CP_WAIT0()   asm volatile("cp.async.wait_group 0;" ::: "memory")

__device__ __forceinline__ uint32_t f2tf32(float x) {
    uint32_t r;
    asm("cvt.rna.tf32.f32 %0, %1;" : "=r"(r) : "f"(x));
    return r;
}

__device__ __forceinline__ void mma_tf32_16x8x8(float c[4], const uint32_t a[4],
                                                uint32_t b0, uint32_t b1) {
    asm volatile(
        "mma.sync.aligned.m16n8k8.row.col.f32.tf32.tf32.f32 "
        "{%0,%1,%2,%3}, {%4,%5,%6,%7}, {%8,%9}, {%0,%1,%2,%3};"
        : "+f"(c[0]), "+f"(c[1]), "+f"(c[2]), "+f"(c[3])
        : "r"(a[0]), "r"(a[1]), "r"(a[2]), "r"(a[3]), "r"(b0), "r"(b1));
}

// ===========================================================================
// 3xTF32 mma.sync GEMM (proven R5):  C[128x128] tile of X @ W^T, K=1024
// ===========================================================================
#define KT   32
#define PAD  36
#define STAGE_F (128*PAD)
#define GEMM_SMEM_BYTES (4*STAGE_F*4)

__device__ __forceinline__ void gemm_mma_tile(const float* __restrict__ X,
                                              const float* __restrict__ W,
                                              int row0, int col0,
                                              float acc[4][4][4])
{
    extern __shared__ float sm[];
    const int tid  = threadIdx.x;
    const int wid  = tid >> 5, lane = tid & 31;
    const int warpM = wid >> 2, warpN = wid & 3;
    const int quad = lane >> 2, tq = lane & 3;

    uint32_t dA[4], dB[4];
    const float* sA[4];
    const float* sB[4];
    const uint32_t smb = smem_u32(sm);
    #pragma unroll
    for (int it = 0; it < 4; it++) {
        int id = it * 256 + tid;
        int r  = id >> 3;
        int c  = id & 7;
        dA[it] = smb + (uint32_t)(r * PAD + c * 4) * 4u;
        dB[it] = dA[it] + STAGE_F * 4u;
        sA[it] = X + (size_t)(row0 + r) * Dm + c * 4;
        sB[it] = W + (size_t)(col0 + r) * Dm + c * 4;
    }
    const uint32_t stageOff = 2u * STAGE_F * 4u;

    const float* As = sm;
    const float* Bs = sm + STAGE_F;
    const int aRow0 = warpM * 64 + quad;
    const int bRow0 = warpN * 32 + quad;

    #pragma unroll
    for (int it = 0; it < 4; it++) { CP16(dA[it], sA[it]); CP16(dB[it], sB[it]); }
    CP_COMMIT();

    const int NST = Dm / KT;
    for (int s = 0; s < NST; s++) {
        const int cur = s & 1;
        if (s + 1 < NST) {
            const uint32_t bo = (uint32_t)((s + 1) & 1) * stageOff;
            const int ko = (s + 1) * KT;
            #pragma unroll
            for (int it = 0; it < 4; it++) {
                CP16(dA[it] + bo, sA[it] + ko);
                CP16(dB[it] + bo, sB[it] + ko);
            }
            CP_COMMIT();
            CP_WAIT1();
        } else {
            CP_WAIT0();
        }
        __syncthreads();

        const float* Ab = As + cur * 2 * STAGE_F;
        const float* Bb = Bs + cur * 2 * STAGE_F;

        #pragma unroll
        for (int kk = 0; kk < 4; kk++) {
            const int k0 = kk * 8 + tq;
            uint32_t ah[4][4], al[4][4], bh[4][2], bl[4][2];
            #pragma unroll
            for (int mi = 0; mi < 4; mi++) {
                const float* p = Ab + (aRow0 + mi * 16) * PAD + k0;
                float v0 = p[0], v1 = p[8 * PAD], v2 = p[4], v3 = p[8 * PAD + 4];
                ah[mi][0] = f2tf32(v0); al[mi][0] = f2tf32(v0 - __uint_as_float(ah[mi][0]));
                ah[mi][1] = f2tf32(v1); al[mi][1] = f2tf32(v1 - __uint_as_float(ah[mi][1]));
                ah[mi][2] = f2tf32(v2); al[mi][2] = f2tf32(v2 - __uint_as_float(ah[mi][2]));
                ah[mi][3] = f2tf32(v3); al[mi][3] = f2tf32(v3 - __uint_as_float(ah[mi][3]));
            }
            #pragma unroll
            for (int ni = 0; ni < 4; ni++) {
                const float* p = Bb + (bRow0 + ni * 8) * PAD + k0;
                float v0 = p[0], v1 = p[4];
                bh[ni][0] = f2tf32(v0); bl[ni][0] = f2tf32(v0 - __uint_as_float(bh[ni][0]));
                bh[ni][1] = f2tf32(v1); bl[ni][1] = f2tf32(v1 - __uint_as_float(bh[ni][1]));
            }
            #pragma unroll
            for (int mi = 0; mi < 4; mi++)
                #pragma unroll
                for (int ni = 0; ni < 4; ni++) {
                    mma_tf32_16x8x8(acc[mi][ni], al[mi], bh[ni][0], bh[ni][1]);
                    mma_tf32_16x8x8(acc[mi][ni], ah[mi], bl[ni][0], bl[ni][1]);
                    mma_tf32_16x8x8(acc[mi][ni], ah[mi], bh[ni][0], bh[ni][1]);
                }
        }
        __syncthreads();
    }
}

__global__ __launch_bounds__(256)
void qkv_mma(const float* __restrict__ X,
             const float* __restrict__ Wq, const float* __restrict__ bq,
             const float* __restrict__ Wk, const float* __restrict__ bk,
             const float* __restrict__ Wv, const float* __restrict__ bv)
{
    const float *W, *bias;
    float* out;
    if (blockIdx.z == 0)      { W = Wq; bias = bq; out = g_q; }
    else if (blockIdx.z == 1) { W = Wk; bias = bk; out = g_k; }
    else                      { W = Wv; bias = bv; out = g_v; }

    float acc[4][4][4];
    #pragma unroll
    for (int mi = 0; mi < 4; mi++)
        #pragma unroll
        for (int ni = 0; ni < 4; ni++)
            #pragma unroll
            for (int j = 0; j < 4; j++) acc[mi][ni][j] = 0.f;

    const int row0 = blockIdx.y * 128;
    const int col0 = blockIdx.x * 128;
    gemm_mma_tile(X, W, row0, col0, acc);

    const int tid  = threadIdx.x;
    const int wid  = tid >> 5, lane = tid & 31;
    const int warpM = wid >> 2, warpN = wid & 3;
    const int quad = lane >> 2, tq = lane & 3;

    #pragma unroll
    for (int mi = 0; mi < 4; mi++) {
        #pragma unroll
        for (int half = 0; half < 2; half++) {
            const int r = row0 + warpM * 64 + mi * 16 + quad + half * 8;
            const int b = r >> 11;
            const int sq = r & 2047;
            #pragma unroll
            for (int ni = 0; ni < 4; ni++) {
                const int c  = col0 + warpN * 32 + ni * 8 + 2 * tq;
                const int h  = c >> 6;
                const int hd = c & 63;
                float2 bb = *(const float2*)&bias[c];
                float2 v;
                v.x = acc[mi][ni][half * 2 + 0] + bb.x;
                v.y = acc[mi][ni][half * 2 + 1] + bb.y;
                *(float2*)(out + (((size_t)(b * Hn + h) * Seq + sq) * Hd + hd)) = v;
            }
        }
    }
}

__global__ __launch_bounds__(256)
void proj_mma(const float* __restrict__ Wo, const float* __restrict__ bo,
              const float* __restrict__ comp, float* __restrict__ out)
{
    float acc[4][4][4];
    #pragma unroll
    for (int mi = 0; mi < 4; mi++)
        #pragma unroll
        for (int ni = 0; ni < 4; ni++)
            #pragma unroll
            for (int j = 0; j < 4; j++) acc[mi][ni][j] = 0.f;

    const int row0 = blockIdx.y * 128;
    const int col0 = blockIdx.x * 128;
    gemm_mma_tile(g_att, Wo, row0, col0, acc);

    const int tid  = threadIdx.x;
    const int wid  = tid >> 5, lane = tid & 31;
    const int warpM = wid >> 2, warpN = wid & 3;
    const int quad = lane >> 2, tq = lane & 3;

    #pragma unroll
    for (int mi = 0; mi < 4; mi++) {
        #pragma unroll
        for (int half = 0; half < 2; half++) {
            const int r = row0 + warpM * 64 + mi * 16 + quad + half * 8;
            #pragma unroll
            for (int ni = 0; ni < 4; ni++) {
                const int c = col0 + warpN * 32 + ni * 8 + 2 * tq;
                float2 bb = *(const float2*)&bo[c];
                float2 cc = *(const float2*)&comp[c];
                float2 v;
                v.x = acc[mi][ni][half * 2 + 0] + bb.x + cc.x;
                v.y = acc[mi][ni][half * 2 + 1] + bb.y + cc.y;
                *(float2*)(out + (size_t)r * Dm + c) = v;
            }
        }
    }
}

// ===========================================================================
// Flash attention, 3xTF32 mma. BM=128, BN=64, 256 threads (8 warps, 16 rows
// each). K/V tiles double-buffered cp.async; per-warp math identical to R5.
// ===========================================================================
#define PQ   68
#define PVV  72
#define QSB_F  (128*PQ)            // Q/P tile: 128 rows
#define KS_F   (64*PQ)             // K tile
#define VS_F   (64*PVV)            // V tile
#define FLASH_SMEM_BYTES ((QSB_F + 2*KS_F + 2*VS_F)*4)  // 106496 B

__global__ __launch_bounds__(256)
void flash_mma()
{
    const int qt = blockIdx.x;           // 0..15 (128-row q tiles)
    const int bh = blockIdx.y;           // 0..63

    const float* Qg = g_q + (size_t)bh * Seq * Hd;
    const float* Kg = g_k + (size_t)bh * Seq * Hd;
    const float* Vg = g_v + (size_t)bh * Seq * Hd;

    extern __shared__ float fs[];
    float* Qs  = fs;                          // 128 x PQ; reused as Ps
    float* Ksb[2] = { fs + QSB_F, fs + QSB_F + KS_F };
    float* Vsb[2] = { fs + QSB_F + 2*KS_F, fs + QSB_F + 2*KS_F + VS_F };

    const int tid  = threadIdx.x;
    const int wid  = tid >> 5, lane = tid & 31;
    const int quad = lane >> 2, tq = lane & 3;
    const int r0   = wid * 16;                // warp rows [r0, r0+16)

    // K/V cp.async slots: 64x64 tile = 1024 chunks, 4 per thread
    int crow[4], cseg[4];
    #pragma unroll
    for (int i = 0; i < 4; i++) {
        int id = i * 256 + tid;
        crow[i] = id >> 4;
        cseg[i] = id & 15;
    }
    const uint32_t qsb = smem_u32(Qs);
    const uint32_t ks0 = smem_u32(Ksb[0]), ks1 = smem_u32(Ksb[1]);
    const uint32_t vs0 = smem_u32(Vsb[0]), vs1 = smem_u32(Vsb[1]);

    // Prologue: Q tile (128x64 = 2048 chunks, 8/thread) + K/V tile 0
    #pragma unroll
    for (int i = 0; i < 8; i++) {
        int id = i * 256 + tid;
        int row = id >> 4, seg = id & 15;
        CP16(qsb + (uint32_t)(row*PQ + seg*4)*4u,
             Qg + (size_t)(qt*128 + row) * Hd + seg*4);
    }
    #pragma unroll
    for (int i = 0; i < 4; i++) {
        CP16(ks0 + (uint32_t)(crow[i]*PQ + cseg[i]*4)*4u,
             Kg + (size_t)(crow[i]) * Hd + cseg[i]*4);
        CP16(vs0 + (uint32_t)(crow[i]*PVV + cseg[i]*4)*4u,
             Vg + (size_t)(crow[i]) * Hd + cseg[i]*4);
    }
    CP_COMMIT();
    CP_WAIT0();
    __syncthreads();

    // Extract Q A-frags (scaled 1/8), split hi/lo. Qs freed -> Ps.
    uint32_t qhi[8][4], qlo[8][4];
    #pragma unroll
    for (int kk = 0; kk < 8; kk++) {
        const int k0 = kk * 8 + tq;
        float v0 = Qs[(r0 + quad)     * PQ + k0]     * 0.125f;
        float v1 = Qs[(r0 + quad + 8) * PQ + k0]     * 0.125f;
        float v2 = Qs[(r0 + quad)     * PQ + k0 + 4] * 0.125f;
        float v3 = Qs[(r0 + quad + 8) * PQ + k0 + 4] * 0.125f;
        qhi[kk][0] = f2tf32(v0); qlo[kk][0] = f2tf32(v0 - __uint_as_float(qhi[kk][0]));
        qhi[kk][1] = f2tf32(v1); qlo[kk][1] = f2tf32(v1 - __uint_as_float(qhi[kk][1]));
        qhi[kk][2] = f2tf32(v2); qlo[kk][2] = f2tf32(v2 - __uint_as_float(qhi[kk][2]));
        qhi[kk][3] = f2tf32(v3); qlo[kk][3] = f2tf32(v3 - __uint_as_float(qhi[kk][3]));
    }
    float* Ps = Qs;

    float m_i[2] = { -1e30f, -1e30f };
    float l_i[2] = { 0.f, 0.f };
    float oacc[8][4];
    #pragma unroll
    for (int ni = 0; ni < 8; ni++)
        #pragma unroll
        for (int j = 0; j < 4; j++) oacc[ni][j] = 0.f;

    const int jend = 2 * qt + 1;              // last KV tile (causal)
    const int ig0  = qt * 128 + r0 + quad;    // global q row (half 0)

    for (int jt = 0; jt <= jend; jt++) {
        __syncthreads();

        const int cur = jt & 1;
        if (jt + 1 <= jend) {
            const uint32_t kd = (jt + 1) & 1 ? ks1 : ks0;
            const uint32_t vd = (jt + 1) & 1 ? vs1 : vs0;
            const size_t roff = (size_t)((jt + 1) * 64);
            #pragma unroll
            for (int i = 0; i < 4; i++) {
                CP16(kd + (uint32_t)(crow[i]*PQ + cseg[i]*4)*4u,
                     Kg + (roff + crow[i]) * Hd + cseg[i]*4);
                CP16(vd + (uint32_t)(crow[i]*PVV + cseg[i]*4)*4u,
                     Vg + (roff + crow[i]) * Hd + cseg[i]*4);
            }
            CP_COMMIT();
            CP_WAIT1();
        } else {
            CP_WAIT0();
        }
        __syncthreads();

        const float* Ks = Ksb[cur];
        const float* Vs = Vsb[cur];

        // ---- S = Q K^T (3xTF32) ----
        float sacc[8][4];
        #pragma unroll
        for (int ni = 0; ni < 8; ni++)
            #pragma unroll
            for (int j = 0; j < 4; j++) sacc[ni][j] = 0.f;

        #pragma unroll
        for (int ni = 0; ni < 8; ni++) {
            const float* kb = Ks + (ni * 8 + quad) * PQ;
            #pragma unroll
            for (int kk = 0; kk < 8; kk++) {
                const int k0 = kk * 8 + tq;
                float v0 = kb[k0], v1 = kb[k0 + 4];
                uint32_t bh0 = f2tf32(v0), bl0 = f2tf32(v0 - __uint_as_float(bh0));
                uint32_t bh1 = f2tf32(v1), bl1 = f2tf32(v1 - __uint_as_float(bh1));
                mma_tf32_16x8x8(sacc[ni], qlo[kk], bh0, bh1);
                mma_tf32_16x8x8(sacc[ni], qhi[kk], bl0, bl1);
                mma_tf32_16x8x8(sacc[ni], qhi[kk], bh0, bh1);
            }
        }

        // ---- causal mask (only the last two tiles can cross the diagonal) ----
        if (jt >= 2 * qt) {
            const int jg0 = jt * 64;
            #pragma unroll
            for (int ni = 0; ni < 8; ni++) {
                const int jg = jg0 + ni * 8 + 2 * tq;
                if (jg     > ig0)      sacc[ni][0] = -1e30f;
                if (jg + 1 > ig0)      sacc[ni][1] = -1e30f;
                if (jg     > ig0 + 8)  sacc[ni][2] = -1e30f;
                if (jg + 1 > ig0 + 8)  sacc[ni][3] = -1e30f;
            }
        }

        // ---- online softmax (rows quad, quad+8; 4-lane reductions) ----
        float mloc0 = -1e30f, mloc1 = -1e30f;
        #pragma unroll
        for (int ni = 0; ni < 8; ni++) {
            mloc0 = fmaxf(mloc0, fmaxf(sacc[ni][0], sacc[ni][1]));
            mloc1 = fmaxf(mloc1, fmaxf(sacc[ni][2], sacc[ni][3]));
        }
        #pragma unroll
        for (int off = 1; off < 4; off <<= 1) {
            mloc0 = fmaxf(mloc0, __shfl_xor_sync(0xffffffffu, mloc0, off));
            mloc1 = fmaxf(mloc1, __shfl_xor_sync(0xffffffffu, mloc1, off));
        }
        const float mnew0 = fmaxf(m_i[0], mloc0);
        const float mnew1 = fmaxf(m_i[1], mloc1);
        const float al0 = __expf(m_i[0] - mnew0);
        const float al1 = __expf(m_i[1] - mnew1);
        float ps0 = 0.f, ps1 = 0.f;
        #pragma unroll
        for (int ni = 0; ni < 8; ni++) {
            sacc[ni][0] = __expf(sacc[ni][0] - mnew0);
            sacc[ni][1] = __expf(sacc[ni][1] - mnew0);
            sacc[ni][2] = __expf(sacc[ni][2] - mnew1);
            sacc[ni][3] = __expf(sacc[ni][3] - mnew1);
            ps0 += sacc[ni][0] + sacc[ni][1];
            ps1 += sacc[ni][2] + sacc[ni][3];
        }
        #pragma unroll
        for (int off = 1; off < 4; off <<= 1) {
            ps0 += __shfl_xor_sync(0xffffffffu, ps0, off);
            ps1 += __shfl_xor_sync(0xffffffffu, ps1, off);
        }
        l_i[0] = l_i[0] * al0 + ps0;  m_i[0] = mnew0;
        l_i[1] = l_i[1] * al1 + ps1;  m_i[1] = mnew1;
        #pragma unroll
        for (int ni = 0; ni < 8; ni++) {
            oacc[ni][0] *= al0; oacc[ni][1] *= al0;
            oacc[ni][2] *= al1; oacc[ni][3] *= al1;
        }

        // ---- store P (warp-local rows) ----
        #pragma unroll
        for (int ni = 0; ni < 8; ni++) {
            *(float2*)&Ps[(r0 + quad)     * PQ + ni * 8 + 2 * tq] =
                make_float2(sacc[ni][0], sacc[ni][1]);
            *(float2*)&Ps[(r0 + quad + 8) * PQ + ni * 8 + 2 * tq] =
                make_float2(sacc[ni][2], sacc[ni][3]);
        }
        __syncwarp();

        // ---- O += P V (3xTF32) ----
        #pragma unroll
        for (int kk = 0; kk < 8; kk++) {
            const int k0 = kk * 8 + tq;
            float p0 = Ps[(r0 + quad)     * PQ + k0];
            float p1 = Ps[(r0 + quad + 8) * PQ + k0];
            float p2 = Ps[(r0 + quad)     * PQ + k0 + 4];
            float p3 = Ps[(r0 + quad + 8) * PQ + k0 + 4];
            uint32_t ph[4], pl[4];
            ph[0] = f2tf32(p0); pl[0] = f2tf32(p0 - __uint_as_float(ph[0]));
            ph[1] = f2tf32(p1); pl[1] = f2tf32(p1 - __uint_as_float(ph[1]));
            ph[2] = f2tf32(p2); pl[2] = f2tf32(p2 - __uint_as_float(ph[2]));
            ph[3] = f2tf32(p3); pl[3] = f2tf32(p3 - __uint_as_float(ph[3]));
            const float* vb0 = Vs + (kk * 8 + tq) * PVV;
            const float* vb1 = Vs + (kk * 8 + tq + 4) * PVV;
            #pragma unroll
            for (int ni = 0; ni < 8; ni++) {
                float v0 = vb0[ni * 8 + quad];
                float v1 = vb1[ni * 8 + quad];
                uint32_t bh0 = f2tf32(v0), bl0 = f2tf32(v0 - __uint_as_float(bh0));
                uint32_t bh1 = f2tf32(v1), bl1 = f2tf32(v1 - __uint_as_float(bh1));
                mma_tf32_16x8x8(oacc[ni], pl, bh0, bh1);
                mma_tf32_16x8x8(oacc[ni], ph, bl0, bl1);
                mma_tf32_16x8x8(oacc[ni], ph, bh0, bh1);
            }
        }
        __syncwarp();   // P reads done before next iteration overwrites Ps
    }

    // ---- normalize + write to [B,S,H,HD] ----
    const int bidx = bh >> 4, h = bh & 15;
    #pragma unroll
    for (int half = 0; half < 2; half++) {
        const float inv = 1.0f / l_i[half];
        const int s = qt * 128 + r0 + quad + half * 8;
        float* dst = g_att + (((size_t)bidx * Seq + s) * Hn + h) * Hd;
        #pragma unroll
        for (int ni = 0; ni < 8; ni++) {
            float2 v = make_float2(oacc[ni][half * 2 + 0] * inv,
                                   oacc[ni][half * 2 + 1] * inv);
            *(float2*)(dst + ni * 8 + 2 * tq) = v;
        }
    }
}

// ---------------------------------------------------------------------------
extern "C" void kernel_launch(void* const* d_in, const int* in_sizes, int n_in,
                              void* d_out, int out_size)
{
    (void)in_sizes; (void)n_in; (void)out_size;
    const float* X    = (const float*)d_in[0];
    const float* Wq   = (const float*)d_in[1];
    const float* bq   = (const float*)d_in[2];
    const float* Wk   = (const float*)d_in[3];
    const float* bk   = (const float*)d_in[4];
    const float* Wv   = (const float*)d_in[5];
    const float* bv   = (const float*)d_in[6];
    const float* Wo   = (const float*)d_in[7];
    const float* bo   = (const float*)d_in[8];
    const float* comp = (const float*)d_in[9];
    float* out = (float*)d_out;

    cudaFuncSetAttribute(qkv_mma,   cudaFuncAttributeMaxDynamicSharedMemorySize, GEMM_SMEM_BYTES);
    cudaFuncSetAttribute(proj_mma,  cudaFuncAttributeMaxDynamicSharedMemorySize, GEMM_SMEM_BYTES);
    cudaFuncSetAttribute(flash_mma, cudaFuncAttributeMaxDynamicSharedMemorySize, FLASH_SMEM_BYTES);

    dim3 gQKV(Dm/128, Mrows/128, 3);     // (8, 64, 3)
    qkv_mma<<<gQKV, 256, GEMM_SMEM_BYTES>>>(X, Wq, bq, Wk, bk, Wv, bv);

    dim3 gFA(Seq/128, Bsz*Hn);           // (16, 64)
    flash_mma<<<gFA, 256, FLASH_SMEM_BYTES>>>();

    dim3 gP(Dm/128, Mrows/128);          // (8, 64)
    proj_mma<<<gP, 256, GEMM_SMEM_BYTES>>>(Wo, bo, comp, out);
}

// round 8
// speedup vs baseline: 1.3134x; 1.1560x over previous
#include <cuda_runtime.h>
#include <cstdint>

#define Bsz 4
#define Seq 2048
#define Dm  1024
#define Hn  16
#define Hd  64
#define Mrows (Bsz*Seq)   // 8192

// Scratch (allocation-free rule: __device__ globals)
// Pre-split operands: hi = tf32(v), lo = tf32(v - hi), both stored as fp32 bits.
__device__ float g_xhi[Mrows*Dm],  g_xlo[Mrows*Dm];     // X split
__device__ float g_whi[4][Dm*Dm],  g_wlo[4][Dm*Dm];     // Wq,Wk,Wv,Wo split
__device__ float g_qhi[Bsz*Hn*Seq*Hd], g_qlo[Bsz*Hn*Seq*Hd];   // [B,H,S,HD]
__device__ float g_khi[Bsz*Hn*Seq*Hd], g_klo[Bsz*Hn*Seq*Hd];   // pre-scaled 1/8
__device__ float g_vhi[Bsz*Hn*Seq*Hd], g_vlo[Bsz*Hn*Seq*Hd];
__device__ float g_ahi[Bsz*Seq*Dm],    g_alo[Bsz*Seq*Dm];      // attention out split

// ===========================================================================
// Common PTX helpers
// ===========================================================================
__device__ __forceinline__ uint32_t smem_u32(const void* p) {
    uint32_t a;
    asm("{ .reg .u64 t; cvta.to.shared.u64 t, %1; cvt.u32.u64 %0, t; }"
        : "=r"(a) : "l"(p));
    return a;
}

#define CP16(dst, src) \
    asm volatile("cp.async.cg.shared.global [%0], [%1], 16;" :: "r"(dst), "l"(src))
#define CP_COMMIT()  asm volatile("cp.async.commit_group;" ::: "memory")
#define CP_WAIT1()   asm volatile("cp.async.wait_group 1;" ::: "memory")
#define CP_WAIT0()   asm volatile("cp.async.wait_group 0;" ::: "memory")

__device__ __forceinline__ uint32_t f2tf32(float x) {
    uint32_t r;
    asm("cvt.rna.tf32.f32 %0, %1;" : "=r"(r) : "f"(x));
    return r;
}
__device__ __forceinline__ uint32_t fau(float x) { return __float_as_uint(x); }

__device__ __forceinline__ void mma_tf32_16x8x8(float c[4], const uint32_t a[4],
                                                uint32_t b0, uint32_t b1) {
    asm volatile(
        "mma.sync.aligned.m16n8k8.row.col.f32.tf32.tf32.f32 "
        "{%0,%1,%2,%3}, {%4,%5,%6,%7}, {%8,%9}, {%0,%1,%2,%3};"
        : "+f"(c[0]), "+f"(c[1]), "+f"(c[2]), "+f"(c[3])
        : "r"(a[0]), "r"(a[1]), "r"(a[2]), "r"(a[3]), "r"(b0), "r"(b1));
}

// ===========================================================================
// Split pre-pass: X and the 4 weight matrices -> hi/lo arrays
// ===========================================================================
__global__ __launch_bounds__(256)
void split_xw(const float* __restrict__ X,
              const float* __restrict__ Wq, const float* __restrict__ Wk,
              const float* __restrict__ Wv, const float* __restrict__ Wo)
{
    const int z = blockIdx.y;
    const float* src;
    float *dhi, *dlo;
    int n4;                      // number of float4s
    if (z == 0)      { src = X;  dhi = g_xhi;    dlo = g_xlo;    n4 = Mrows*Dm/4; }
    else if (z == 1) { src = Wq; dhi = g_whi[0]; dlo = g_wlo[0]; n4 = Dm*Dm/4; }
    else if (z == 2) { src = Wk; dhi = g_whi[1]; dlo = g_wlo[1]; n4 = Dm*Dm/4; }
    else if (z == 3) { src = Wv; dhi = g_whi[2]; dlo = g_wlo[2]; n4 = Dm*Dm/4; }
    else             { src = Wo; dhi = g_whi[3]; dlo = g_wlo[3]; n4 = Dm*Dm/4; }

    for (int i = blockIdx.x * blockDim.x + threadIdx.x; i < n4;
         i += gridDim.x * blockDim.x) {
        float4 v = ((const float4*)src)[i];
        float4 h, l;
        h.x = __uint_as_float(f2tf32(v.x)); l.x = __uint_as_float(f2tf32(v.x - h.x));
        h.y = __uint_as_float(f2tf32(v.y)); l.y = __uint_as_float(f2tf32(v.y - h.y));
        h.z = __uint_as_float(f2tf32(v.z)); l.z = __uint_as_float(f2tf32(v.z - h.z));
        h.w = __uint_as_float(f2tf32(v.w)); l.w = __uint_as_float(f2tf32(v.w - h.w));
        ((float4*)dhi)[i] = h;
        ((float4*)dlo)[i] = l;
    }
}

// ===========================================================================
// 3xTF32 GEMM on pre-split operands. C[128x128] tile, K=1024, KT=32 stages.
// Stage = Ahi|Alo|Bhi|Blo tiles (128 x PAD floats each), double-buffered.
// ===========================================================================
#define KT   32
#define PAD  36
#define TILE_F   (128*PAD)          // 4608 floats per tile
#define QSTAGE_F (4*TILE_F)
#define GEMM_SMEM_BYTES (2*QSTAGE_F*4)   // 147456 B

__device__ __forceinline__ void gemm_mma_tile_ps(const float* __restrict__ Ahi_g,
                                                 const float* __restrict__ Alo_g,
                                                 const float* __restrict__ Bhi_g,
                                                 const float* __restrict__ Blo_g,
                                                 int row0, int col0,
                                                 float acc[4][4][4])
{
    extern __shared__ float sm[];
    const int tid  = threadIdx.x;
    const int wid  = tid >> 5, lane = tid & 31;
    const int warpM = wid >> 2, warpN = wid & 3;
    const int quad = lane >> 2, tq = lane & 3;

    uint32_t dst[4];
    size_t offA[4], offB[4];
    const uint32_t smb = smem_u32(sm);
    #pragma unroll
    for (int it = 0; it < 4; it++) {
        int id = it * 256 + tid;
        int r  = id >> 3;
        int c  = id & 7;
        dst[it] = smb + (uint32_t)(r * PAD + c * 4) * 4u;
        offA[it] = (size_t)(row0 + r) * Dm + c * 4;
        offB[it] = (size_t)(col0 + r) * Dm + c * 4;
    }
    const uint32_t TB       = TILE_F * 4u;      // tile stride (bytes)
    const uint32_t stageOff = QSTAGE_F * 4u;

    const int aRow0 = warpM * 64 + quad;
    const int bRow0 = warpN * 32 + quad;

    // Prologue: stage 0
    #pragma unroll
    for (int it = 0; it < 4; it++) {
        CP16(dst[it],          Ahi_g + offA[it]);
        CP16(dst[it] + TB,     Alo_g + offA[it]);
        CP16(dst[it] + 2*TB,   Bhi_g + offB[it]);
        CP16(dst[it] + 3*TB,   Blo_g + offB[it]);
    }
    CP_COMMIT();

    const int NST = Dm / KT;
    for (int s = 0; s < NST; s++) {
        const int cur = s & 1;
        if (s + 1 < NST) {
            const uint32_t bo = (uint32_t)((s + 1) & 1) * stageOff;
            const int ko = (s + 1) * KT;
            #pragma unroll
            for (int it = 0; it < 4; it++) {
                CP16(dst[it] + bo,          Ahi_g + offA[it] + ko);
                CP16(dst[it] + bo + TB,     Alo_g + offA[it] + ko);
                CP16(dst[it] + bo + 2*TB,   Bhi_g + offB[it] + ko);
                CP16(dst[it] + bo + 3*TB,   Blo_g + offB[it] + ko);
            }
            CP_COMMIT();
            CP_WAIT1();
        } else {
            CP_WAIT0();
        }
        __syncthreads();

        const float* base = sm + cur * QSTAGE_F;
        const float* Ahb = base;
        const float* Alb = base + TILE_F;
        const float* Bhb = base + 2 * TILE_F;
        const float* Blb = base + 3 * TILE_F;

        #pragma unroll
        for (int kk = 0; kk < 4; kk++) {
            const int k0 = kk * 8 + tq;
            uint32_t ah[4][4], al[4][4], bh[4][2], bl[4][2];
            #pragma unroll
            for (int mi = 0; mi < 4; mi++) {
                const float* ph = Ahb + (aRow0 + mi * 16) * PAD + k0;
                const float* pl = Alb + (aRow0 + mi * 16) * PAD + k0;
                ah[mi][0] = fau(ph[0]); ah[mi][1] = fau(ph[8*PAD]);
                ah[mi][2] = fau(ph[4]); ah[mi][3] = fau(ph[8*PAD+4]);
                al[mi][0] = fau(pl[0]); al[mi][1] = fau(pl[8*PAD]);
                al[mi][2] = fau(pl[4]); al[mi][3] = fau(pl[8*PAD+4]);
            }
            #pragma unroll
            for (int ni = 0; ni < 4; ni++) {
                const float* ph = Bhb + (bRow0 + ni * 8) * PAD + k0;
                const float* pl = Blb + (bRow0 + ni * 8) * PAD + k0;
                bh[ni][0] = fau(ph[0]); bh[ni][1] = fau(ph[4]);
                bl[ni][0] = fau(pl[0]); bl[ni][1] = fau(pl[4]);
            }
            #pragma unroll
            for (int mi = 0; mi < 4; mi++)
                #pragma unroll
                for (int ni = 0; ni < 4; ni++) {
                    mma_tf32_16x8x8(acc[mi][ni], al[mi], bh[ni][0], bh[ni][1]);
                    mma_tf32_16x8x8(acc[mi][ni], ah[mi], bl[ni][0], bl[ni][1]);
                    mma_tf32_16x8x8(acc[mi][ni], ah[mi], bh[ni][0], bh[ni][1]);
                }
        }
        __syncthreads();
    }
}

// ===========================================================================
// QKV projection; epilogue writes hi/lo Q/K/V (K pre-scaled by 1/8)
// ===========================================================================
__global__ __launch_bounds__(256)
void qkv_mma(const float* __restrict__ bq, const float* __restrict__ bk,
             const float* __restrict__ bv)
{
    const float* bias;
    float *ohi, *olo;
    float scale;
    if (blockIdx.z == 0)      { bias = bq; ohi = g_qhi; olo = g_qlo; scale = 1.0f;   }
    else if (blockIdx.z == 1) { bias = bk; ohi = g_khi; olo = g_klo; scale = 0.125f; }
    else                      { bias = bv; ohi = g_vhi; olo = g_vlo; scale = 1.0f;   }

    float acc[4][4][4];
    #pragma unroll
    for (int mi = 0; mi < 4; mi++)
        #pragma unroll
        for (int ni = 0; ni < 4; ni++)
            #pragma unroll
            for (int j = 0; j < 4; j++) acc[mi][ni][j] = 0.f;

    const int row0 = blockIdx.y * 128;
    const int col0 = blockIdx.x * 128;
    gemm_mma_tile_ps(g_xhi, g_xlo, g_whi[blockIdx.z], g_wlo[blockIdx.z],
                     row0, col0, acc);

    const int tid  = threadIdx.x;
    const int wid  = tid >> 5, lane = tid & 31;
    const int warpM = wid >> 2, warpN = wid & 3;
    const int quad = lane >> 2, tq = lane & 3;

    #pragma unroll
    for (int mi = 0; mi < 4; mi++) {
        #pragma unroll
        for (int half = 0; half < 2; half++) {
            const int r = row0 + warpM * 64 + mi * 16 + quad + half * 8;
            const int b = r >> 11;
            const int sq = r & 2047;
            #pragma unroll
            for (int ni = 0; ni < 4; ni++) {
                const int c  = col0 + warpN * 32 + ni * 8 + 2 * tq;
                const int h  = c >> 6;
                const int hd = c & 63;
                float2 bb = *(const float2*)&bias[c];
                float vx = (acc[mi][ni][half*2+0] + bb.x) * scale;
                float vy = (acc[mi][ni][half*2+1] + bb.y) * scale;
                float hx = __uint_as_float(f2tf32(vx));
                float hy = __uint_as_float(f2tf32(vy));
                float lx = __uint_as_float(f2tf32(vx - hx));
                float ly = __uint_as_float(f2tf32(vy - hy));
                const size_t o = (((size_t)(b * Hn + h) * Seq + sq) * Hd + hd);
                *(float2*)(ohi + o) = make_float2(hx, hy);
                *(float2*)(olo + o) = make_float2(lx, ly);
            }
        }
    }
}

// ===========================================================================
// Output projection: out = att @ Wo^T + bo + comp (att pre-split by flash)
// ===========================================================================
__global__ __launch_bounds__(256)
void proj_mma(const float* __restrict__ bo, const float* __restrict__ comp,
              float* __restrict__ out)
{
    float acc[4][4][4];
    #pragma unroll
    for (int mi = 0; mi < 4; mi++)
        #pragma unroll
        for (int ni = 0; ni < 4; ni++)
            #pragma unroll
            for (int j = 0; j < 4; j++) acc[mi][ni][j] = 0.f;

    const int row0 = blockIdx.y * 128;
    const int col0 = blockIdx.x * 128;
    gemm_mma_tile_ps(g_ahi, g_alo, g_whi[3], g_wlo[3], row0, col0, acc);

    const int tid  = threadIdx.x;
    const int wid  = tid >> 5, lane = tid & 31;
    const int warpM = wid >> 2, warpN = wid & 3;
    const int quad = lane >> 2, tq = lane & 3;

    #pragma unroll
    for (int mi = 0; mi < 4; mi++) {
        #pragma unroll
        for (int half = 0; half < 2; half++) {
            const int r = row0 + warpM * 64 + mi * 16 + quad + half * 8;
            #pragma unroll
            for (int ni = 0; ni < 4; ni++) {
                const int c = col0 + warpN * 32 + ni * 8 + 2 * tq;
                float2 bb = *(const float2*)&bo[c];
                float2 cc = *(const float2*)&comp[c];
                float2 v;
                v.x = acc[mi][ni][half * 2 + 0] + bb.x + cc.x;
                v.y = acc[mi][ni][half * 2 + 1] + bb.y + cc.y;
                *(float2*)(out + (size_t)r * Dm + c) = v;
            }
        }
    }
}

// ===========================================================================
// Flash attention, 3xTF32 on pre-split Q/K/V. BM=128, BN=64, 256 threads.
// Stage = Khi|Klo|Vhi|Vlo, double-buffered. P split in-loop (4 vals/warp/kk).
// ===========================================================================
#define PQ   68
#define PVV  72
#define QSB_F  (128*PQ)                  // Q staging / P tile
#define KS_F   (64*PQ)
#define VS_F   (64*PVV)
#define FSTG_F (2*KS_F + 2*VS_F)         // 17920 floats per stage
#define FLASH_SMEM_BYTES ((QSB_F + 2*FSTG_F)*4)   // 178176 B

__global__ __launch_bounds__(256)
void flash_mma()
{
    const int qt = blockIdx.x;           // 0..15
    const int bh = blockIdx.y;           // 0..63
    const size_t bho = (size_t)bh * Seq * Hd;

    extern __shared__ float fs[];
    float* Qs = fs;                      // reused as Ps
    float* stage0 = fs + QSB_F;

    const int tid  = threadIdx.x;
    const int wid  = tid >> 5, lane = tid & 31;
    const int quad = lane >> 2, tq = lane & 3;
    const int r0   = wid * 16;

    // K/V cp.async slots: 64x64 tile = 1024 chunks, 4/thread
    uint32_t kdo[4], vdo[4];
    size_t srco[4];
    #pragma unroll
    for (int i = 0; i < 4; i++) {
        int id = i * 256 + tid;
        int row = id >> 4, seg = id & 15;
        kdo[i]  = (uint32_t)(row * PQ  + seg * 4) * 4u;
        vdo[i]  = (uint32_t)(row * PVV + seg * 4) * 4u;
        srco[i] = (size_t)row * Hd + seg * 4;
    }
    const uint32_t qsb = smem_u32(Qs);
    const uint32_t st0 = smem_u32(stage0);
    const uint32_t KSB = KS_F * 4u, VSB = VS_F * 4u;
    const uint32_t stgB = FSTG_F * 4u;

    // ---- Prologue phase 1: Qhi + KV stage 0 ----
    #pragma unroll
    for (int i = 0; i < 8; i++) {
        int id = i * 256 + tid;
        int row = id >> 4, seg = id & 15;
        CP16(qsb + (uint32_t)(row*PQ + seg*4)*4u,
             g_qhi + bho + (size_t)(qt*128 + row) * Hd + seg*4);
    }
    #pragma unroll
    for (int i = 0; i < 4; i++) {
        CP16(st0 + kdo[i],             g_khi + bho + srco[i]);
        CP16(st0 + KSB + kdo[i],       g_klo + bho + srco[i]);
        CP16(st0 + 2*KSB + vdo[i],     g_vhi + bho + srco[i]);
        CP16(st0 + 2*KSB + VSB + vdo[i], g_vlo + bho + srco[i]);
    }
    CP_COMMIT();
    CP_WAIT0();
    __syncthreads();

    uint32_t qhi[8][4], qlo[8][4];
    #pragma unroll
    for (int kk = 0; kk < 8; kk++) {
        const int k0 = kk * 8 + tq;
        qhi[kk][0] = fau(Qs[(r0 + quad)     * PQ + k0]);
        qhi[kk][1] = fau(Qs[(r0 + quad + 8) * PQ + k0]);
        qhi[kk][2] = fau(Qs[(r0 + quad)     * PQ + k0 + 4]);
        qhi[kk][3] = fau(Qs[(r0 + quad + 8) * PQ + k0 + 4]);
    }
    __syncthreads();

    // ---- Prologue phase 2: Qlo ----
    #pragma unroll
    for (int i = 0; i < 8; i++) {
        int id = i * 256 + tid;
        int row = id >> 4, seg = id & 15;
        CP16(qsb + (uint32_t)(row*PQ + seg*4)*4u,
             g_qlo + bho + (size_t)(qt*128 + row) * Hd + seg*4);
    }
    CP_COMMIT();
    CP_WAIT0();
    __syncthreads();
    #pragma unroll
    for (int kk = 0; kk < 8; kk++) {
        const int k0 = kk * 8 + tq;
        qlo[kk][0] = fau(Qs[(r0 + quad)     * PQ + k0]);
        qlo[kk][1] = fau(Qs[(r0 + quad + 8) * PQ + k0]);
        qlo[kk][2] = fau(Qs[(r0 + quad)     * PQ + k0 + 4]);
        qlo[kk][3] = fau(Qs[(r0 + quad + 8) * PQ + k0 + 4]);
    }
    float* Ps = Qs;   // warp-private rows; no cross-warp hazard

    float m_i[2] = { -1e30f, -1e30f };
    float l_i[2] = { 0.f, 0.f };
    float oacc[8][4];
    #pragma unroll
    for (int ni = 0; ni < 8; ni++)
        #pragma unroll
        for (int j = 0; j < 4; j++) oacc[ni][j] = 0.f;

    const int jend = 2 * qt + 1;
    const int ig0  = qt * 128 + r0 + quad;

    for (int jt = 0; jt <= jend; jt++) {
        __syncthreads();

        const int cur = jt & 1;
        if (jt + 1 <= jend) {
            const uint32_t sb = st0 + (uint32_t)((jt + 1) & 1) * stgB;
            const size_t ro = (size_t)((jt + 1) * 64) * Hd;
            #pragma unroll
            for (int i = 0; i < 4; i++) {
                CP16(sb + kdo[i],               g_khi + bho + ro + srco[i]);
                CP16(sb + KSB + kdo[i],         g_klo + bho + ro + srco[i]);
                CP16(sb + 2*KSB + vdo[i],       g_vhi + bho + ro + srco[i]);
                CP16(sb + 2*KSB + VSB + vdo[i], g_vlo + bho + ro + srco[i]);
            }
            CP_COMMIT();
            CP_WAIT1();
        } else {
            CP_WAIT0();
        }
        __syncthreads();

        const float* base = stage0 + cur * FSTG_F;
        const float* Khi = base;
        const float* Klo = base + KS_F;
        const float* Vhi = base + 2 * KS_F;
        const float* Vlo = base + 2 * KS_F + VS_F;

        // ---- S = Q K^T (3xTF32, pre-split) ----
        float sacc[8][4];
        #pragma unroll
        for (int ni = 0; ni < 8; ni++)
            #pragma unroll
            for (int j = 0; j < 4; j++) sacc[ni][j] = 0.f;

        #pragma unroll
        for (int ni = 0; ni < 8; ni++) {
            const float* kh = Khi + (ni * 8 + quad) * PQ;
            const float* kl = Klo + (ni * 8 + quad) * PQ;
            #pragma unroll
            for (int kk = 0; kk < 8; kk++) {
                const int k0 = kk * 8 + tq;
                uint32_t bh0 = fau(kh[k0]), bh1 = fau(kh[k0 + 4]);
                uint32_t bl0 = fau(kl[k0]), bl1 = fau(kl[k0 + 4]);
                mma_tf32_16x8x8(sacc[ni], qlo[kk], bh0, bh1);
                mma_tf32_16x8x8(sacc[ni], qhi[kk], bl0, bl1);
                mma_tf32_16x8x8(sacc[ni], qhi[kk], bh0, bh1);
            }
        }

        // ---- causal mask ----
        if (jt >= 2 * qt) {
            const int jg0 = jt * 64;
            #pragma unroll
            for (int ni = 0; ni < 8; ni++) {
                const int jg = jg0 + ni * 8 + 2 * tq;
                if (jg     > ig0)      sacc[ni][0] = -1e30f;
                if (jg + 1 > ig0)      sacc[ni][1] = -1e30f;
                if (jg     > ig0 + 8)  sacc[ni][2] = -1e30f;
                if (jg + 1 > ig0 + 8)  sacc[ni][3] = -1e30f;
            }
        }

        // ---- online softmax ----
        float mloc0 = -1e30f, mloc1 = -1e30f;
        #pragma unroll
        for (int ni = 0; ni < 8; ni++) {
            mloc0 = fmaxf(mloc0, fmaxf(sacc[ni][0], sacc[ni][1]));
            mloc1 = fmaxf(mloc1, fmaxf(sacc[ni][2], sacc[ni][3]));
        }
        #pragma unroll
        for (int off = 1; off < 4; off <<= 1) {
            mloc0 = fmaxf(mloc0, __shfl_xor_sync(0xffffffffu, mloc0, off));
            mloc1 = fmaxf(mloc1, __shfl_xor_sync(0xffffffffu, mloc1, off));
        }
        const float mnew0 = fmaxf(m_i[0], mloc0);
        const float mnew1 = fmaxf(m_i[1], mloc1);
        const float al0 = __expf(m_i[0] - mnew0);
        const float al1 = __expf(m_i[1] - mnew1);
        float ps0 = 0.f, ps1 = 0.f;
        #pragma unroll
        for (int ni = 0; ni < 8; ni++) {
            sacc[ni][0] = __expf(sacc[ni][0] - mnew0);
            sacc[ni][1] = __expf(sacc[ni][1] - mnew0);
            sacc[ni][2] = __expf(sacc[ni][2] - mnew1);
            sacc[ni][3] = __expf(sacc[ni][3] - mnew1);
            ps0 += sacc[ni][0] + sacc[ni][1];
            ps1 += sacc[ni][2] + sacc[ni][3];
        }
        #pragma unroll
        for (int off = 1; off < 4; off <<= 1) {
            ps0 += __shfl_xor_sync(0xffffffffu, ps0, off);
            ps1 += __shfl_xor_sync(0xffffffffu, ps1, off);
        }
        l_i[0] = l_i[0] * al0 + ps0;  m_i[0] = mnew0;
        l_i[1] = l_i[1] * al1 + ps1;  m_i[1] = mnew1;
        #pragma unroll
        for (int ni = 0; ni < 8; ni++) {
            oacc[ni][0] *= al0; oacc[ni][1] *= al0;
            oacc[ni][2] *= al1; oacc[ni][3] *= al1;
        }

        // ---- store P ----
        #pragma unroll
        for (int ni = 0; ni < 8; ni++) {
            *(float2*)&Ps[(r0 + quad)     * PQ + ni * 8 + 2 * tq] =
                make_float2(sacc[ni][0], sacc[ni][1]);
            *(float2*)&Ps[(r0 + quad + 8) * PQ + ni * 8 + 2 * tq] =
                make_float2(sacc[ni][2], sacc[ni][3]);
        }
        __syncwarp();

        // ---- O += P V (P split in-loop, V pre-split) ----
        #pragma unroll
        for (int kk = 0; kk < 8; kk++) {
            const int k0 = kk * 8 + tq;
            float p0 = Ps[(r0 + quad)     * PQ + k0];
            float p1 = Ps[(r0 + quad + 8) * PQ + k0];
            float p2 = Ps[(r0 + quad)     * PQ + k0 + 4];
            float p3 = Ps[(r0 + quad + 8) * PQ + k0 + 4];
            uint32_t ph[4], pl[4];
            ph[0] = f2tf32(p0); pl[0] = f2tf32(p0 - __uint_as_float(ph[0]));
            ph[1] = f2tf32(p1); pl[1] = f2tf32(p1 - __uint_as_float(ph[1]));
            ph[2] = f2tf32(p2); pl[2] = f2tf32(p2 - __uint_as_float(ph[2]));
            ph[3] = f2tf32(p3); pl[3] = f2tf32(p3 - __uint_as_float(ph[3]));
            const float* vh0 = Vhi + (kk * 8 + tq) * PVV;
            const float* vh1 = Vhi + (kk * 8 + tq + 4) * PVV;
            const float* vl0 = Vlo + (kk * 8 + tq) * PVV;
            const float* vl1 = Vlo + (kk * 8 + tq + 4) * PVV;
            #pragma unroll
            for (int ni = 0; ni < 8; ni++) {
                uint32_t bh0 = fau(vh0[ni * 8 + quad]);
                uint32_t bh1 = fau(vh1[ni * 8 + quad]);
                uint32_t bl0 = fau(vl0[ni * 8 + quad]);
                uint32_t bl1 = fau(vl1[ni * 8 + quad]);
                mma_tf32_16x8x8(oacc[ni], pl, bh0, bh1);
                mma_tf32_16x8x8(oacc[ni], ph, bl0, bl1);
                mma_tf32_16x8x8(oacc[ni], ph, bh0, bh1);
            }
        }
        __syncwarp();
    }

    // ---- normalize + write hi/lo att to [B,S,H,HD] ----
    const int bidx = bh >> 4, h = bh & 15;
    #pragma unroll
    for (int half = 0; half < 2; half++) {
        const float inv = 1.0f / l_i[half];
        const int s = qt * 128 + r0 + quad + half * 8;
        const size_t dof = ((size_t)bidx * Seq + s) * Hn * Hd + (size_t)h * Hd;
        #pragma unroll
        for (int ni = 0; ni < 8; ni++) {
            float vx = oacc[ni][half * 2 + 0] * inv;
            float vy = oacc[ni][half * 2 + 1] * inv;
            float hx = __uint_as_float(f2tf32(vx));
            float hy = __uint_as_float(f2tf32(vy));
            float lx = __uint_as_float(f2tf32(vx - hx));
            float ly = __uint_as_float(f2tf32(vy - hy));
            *(float2*)(g_ahi + dof + ni * 8 + 2 * tq) = make_float2(hx, hy);
            *(float2*)(g_alo + dof + ni * 8 + 2 * tq) = make_float2(lx, ly);
        }
    }
}

// ---------------------------------------------------------------------------
extern "C" void kernel_launch(void* const* d_in, const int* in_sizes, int n_in,
                              void* d_out, int out_size)
{
    (void)in_sizes; (void)n_in; (void)out_size;
    const float* X    = (const float*)d_in[0];
    const float* Wq   = (const float*)d_in[1];
    const float* bq   = (const float*)d_in[2];
    const float* Wk   = (const float*)d_in[3];
    const float* bk   = (const float*)d_in[4];
    const float* Wv   = (const float*)d_in[5];
    const float* bv   = (const float*)d_in[6];
    const float* Wo   = (const float*)d_in[7];
    const float* bo   = (const float*)d_in[8];
    const float* comp = (const float*)d_in[9];
    float* out = (float*)d_out;

    cudaFuncSetAttribute(qkv_mma,   cudaFuncAttributeMaxDynamicSharedMemorySize, GEMM_SMEM_BYTES);
    cudaFuncSetAttribute(proj_mma,  cudaFuncAttributeMaxDynamicSharedMemorySize, GEMM_SMEM_BYTES);
    cudaFuncSetAttribute(flash_mma, cudaFuncAttributeMaxDynamicSharedMemorySize, FLASH_SMEM_BYTES);

    dim3 gS(512, 5);                     // split X + 4 W's
    split_xw<<<gS, 256>>>(X, Wq, Wk, Wv, Wo);

    dim3 gQKV(Dm/128, Mrows/128, 3);     // (8, 64, 3)
    qkv_mma<<<gQKV, 256, GEMM_SMEM_BYTES>>>(bq, bk, bv);

    dim3 gFA(Seq/128, Bsz*Hn);           // (16, 64)
    flash_mma<<<gFA, 256, FLASH_SMEM_BYTES>>>();

    dim3 gP(Dm/128, Mrows/128);          // (8, 64)
    proj_mma<<<gP, 256, GEMM_SMEM_BYTES>>>(bo, comp, out);
}

// round 9
// speedup vs baseline: 1.8969x; 1.4442x over previous
#include <cuda_runtime.h>
#include <cuda_bf16.h>
#include <cstdint>

#define Bsz 4
#define Seq 2048
#define Dm  1024
#define Hn  16
#define Hd  64
#define Mrows (Bsz*Seq)   // 8192

// Scratch (allocation-free rule: __device__ globals)
// bf16 hi/lo planes for dense-GEMM operands:
__device__ __nv_bfloat16 g_xhi[Mrows*Dm],  g_xlo[Mrows*Dm];
__device__ __nv_bfloat16 g_whi[4][Dm*Dm],  g_wlo[4][Dm*Dm];
__device__ __nv_bfloat16 g_ahi[Bsz*Seq*Dm], g_alo[Bsz*Seq*Dm];
// tf32 hi/lo fp32 planes for flash (proven R8 path):
__device__ float g_qhi[Bsz*Hn*Seq*Hd], g_qlo[Bsz*Hn*Seq*Hd];
__device__ float g_khi[Bsz*Hn*Seq*Hd], g_klo[Bsz*Hn*Seq*Hd];   // pre-scaled 1/8
__device__ float g_vhi[Bsz*Hn*Seq*Hd], g_vlo[Bsz*Hn*Seq*Hd];

// ===========================================================================
// Common PTX helpers
// ===========================================================================
__device__ __forceinline__ uint32_t smem_u32(const void* p) {
    uint32_t a;
    asm("{ .reg .u64 t; cvta.to.shared.u64 t, %1; cvt.u32.u64 %0, t; }"
        : "=r"(a) : "l"(p));
    return a;
}

#define CP16(dst, src) \
    asm volatile("cp.async.cg.shared.global [%0], [%1], 16;" :: "r"(dst), "l"(src))
#define CP_COMMIT()  asm volatile("cp.async.commit_group;" ::: "memory")
#define CP_WAIT1()   asm volatile("cp.async.wait_group 1;" ::: "memory")
#define CP_WAIT0()   asm volatile("cp.async.wait_group 0;" ::: "memory")

__device__ __forceinline__ uint32_t f2tf32(float x) {
    uint32_t r;
    asm("cvt.rna.tf32.f32 %0, %1;" : "=r"(r) : "f"(x));
    return r;
}
__device__ __forceinline__ uint32_t fau(float x) { return __float_as_uint(x); }

__device__ __forceinline__ void mma_tf32_16x8x8(float c[4], const uint32_t a[4],
                                                uint32_t b0, uint32_t b1) {
    asm volatile(
        "mma.sync.aligned.m16n8k8.row.col.f32.tf32.tf32.f32 "
        "{%0,%1,%2,%3}, {%4,%5,%6,%7}, {%8,%9}, {%0,%1,%2,%3};"
        : "+f"(c[0]), "+f"(c[1]), "+f"(c[2]), "+f"(c[3])
        : "r"(a[0]), "r"(a[1]), "r"(a[2]), "r"(a[3]), "r"(b0), "r"(b1));
}

__device__ __forceinline__ void mma_bf16_16x8x16(float c[4], const uint32_t a[4],
                                                 uint32_t b0, uint32_t b1) {
    asm volatile(
        "mma.sync.aligned.m16n8k16.row.col.f32.bf16.bf16.f32 "
        "{%0,%1,%2,%3}, {%4,%5,%6,%7}, {%8,%9}, {%0,%1,%2,%3};"
        : "+f"(c[0]), "+f"(c[1]), "+f"(c[2]), "+f"(c[3])
        : "r"(a[0]), "r"(a[1]), "r"(a[2]), "r"(a[3]), "r"(b0), "r"(b1));
}

// ===========================================================================
// Split pre-pass: X and 4 W matrices -> bf16 hi/lo planes
// ===========================================================================
__global__ __launch_bounds__(256)
void split_xw(const float* __restrict__ X,
              const float* __restrict__ Wq, const float* __restrict__ Wk,
              const float* __restrict__ Wv, const float* __restrict__ Wo)
{
    const int z = blockIdx.y;
    const float* src;
    __nv_bfloat16 *dhi, *dlo;
    int n4;
    if (z == 0)      { src = X;  dhi = g_xhi;    dlo = g_xlo;    n4 = Mrows*Dm/4; }
    else if (z == 1) { src = Wq; dhi = g_whi[0]; dlo = g_wlo[0]; n4 = Dm*Dm/4; }
    else if (z == 2) { src = Wk; dhi = g_whi[1]; dlo = g_wlo[1]; n4 = Dm*Dm/4; }
    else if (z == 3) { src = Wv; dhi = g_whi[2]; dlo = g_wlo[2]; n4 = Dm*Dm/4; }
    else             { src = Wo; dhi = g_whi[3]; dlo = g_wlo[3]; n4 = Dm*Dm/4; }

    for (int i = blockIdx.x * blockDim.x + threadIdx.x; i < n4;
         i += gridDim.x * blockDim.x) {
        float4 v = ((const float4*)src)[i];
        __nv_bfloat16 h0 = __float2bfloat16_rn(v.x);
        __nv_bfloat16 h1 = __float2bfloat16_rn(v.y);
        __nv_bfloat16 h2 = __float2bfloat16_rn(v.z);
        __nv_bfloat16 h3 = __float2bfloat16_rn(v.w);
        __nv_bfloat16 l0 = __float2bfloat16_rn(v.x - __bfloat162float(h0));
        __nv_bfloat16 l1 = __float2bfloat16_rn(v.y - __bfloat162float(h1));
        __nv_bfloat16 l2 = __float2bfloat16_rn(v.z - __bfloat162float(h2));
        __nv_bfloat16 l3 = __float2bfloat16_rn(v.w - __bfloat162float(h3));
        __nv_bfloat162 hp0 = {h0, h1}, hp1 = {h2, h3};
        __nv_bfloat162 lp0 = {l0, l1}, lp1 = {l2, l3};
        uint2 hw = { *(uint32_t*)&hp0, *(uint32_t*)&hp1 };
        uint2 lw = { *(uint32_t*)&lp0, *(uint32_t*)&lp1 };
        *(uint2*)&dhi[4*i] = hw;
        *(uint2*)&dlo[4*i] = lw;
    }
}

// ===========================================================================
// 3xBF16 GEMM on pre-split bf16 planes. C[128x128] tile, K=1024, KT=32.
// Stage = Ahi|Alo|Bhi|Blo (128 rows x 80B each), double-buffered.
// 8 warps = 2(M) x 4(N); per warp 64x32; m16n8k16 fragments.
// ===========================================================================
#define KTB   32
#define PADB  40                      // bf16 elems per row (80 B, conflict-free)
#define PLANE_B (128*PADB*2)          // 10240 bytes per plane
#define STG_B   (4*PLANE_B)           // 40960 bytes per stage
#define GEMM_SMEM_BYTES (2*STG_B)     // 81920

__device__ __forceinline__ void gemm_bf16_tile(const __nv_bfloat16* __restrict__ Ahi_g,
                                               const __nv_bfloat16* __restrict__ Alo_g,
                                               const __nv_bfloat16* __restrict__ Bhi_g,
                                               const __nv_bfloat16* __restrict__ Blo_g,
                                               int row0, int col0,
                                               float acc[4][4][4])
{
    extern __shared__ char smc[];
    const int tid  = threadIdx.x;
    const int wid  = tid >> 5, lane = tid & 31;
    const int warpM = wid >> 2, warpN = wid & 3;
    const int quad = lane >> 2, tq = lane & 3;

    // cp.async: per plane 512 chunks (16B), 2 per thread
    uint32_t dof[2];
    size_t offA[2], offB[2];
    const uint32_t smb = smem_u32(smc);
    #pragma unroll
    for (int it = 0; it < 2; it++) {
        int id = it * 256 + tid;        // 0..511
        int r  = id >> 2;               // row 0..127
        int c  = id & 3;                // 16B chunk (8 bf16)
        dof[it]  = smb + (uint32_t)(r * 80 + c * 16);
        offA[it] = (size_t)(row0 + r) * Dm + c * 8;
        offB[it] = (size_t)(col0 + r) * Dm + c * 8;
    }

    const int aRow0 = warpM * 64 + quad;
    const int bRow0 = warpN * 32 + quad;

    // Prologue: stage 0
    #pragma unroll
    for (int it = 0; it < 2; it++) {
        CP16(dof[it],               Ahi_g + offA[it]);
        CP16(dof[it] +   PLANE_B,   Alo_g + offA[it]);
        CP16(dof[it] + 2*PLANE_B,   Bhi_g + offB[it]);
        CP16(dof[it] + 3*PLANE_B,   Blo_g + offB[it]);
    }
    CP_COMMIT();

    const int NST = Dm / KTB;           // 32 stages
    for (int s = 0; s < NST; s++) {
        const int cur = s & 1;
        if (s + 1 < NST) {
            const uint32_t bo = (uint32_t)((s + 1) & 1) * STG_B;
            const int ko = (s + 1) * KTB;
            #pragma unroll
            for (int it = 0; it < 2; it++) {
                CP16(dof[it] + bo,               Ahi_g + offA[it] + ko);
                CP16(dof[it] + bo +   PLANE_B,   Alo_g + offA[it] + ko);
                CP16(dof[it] + bo + 2*PLANE_B,   Bhi_g + offB[it] + ko);
                CP16(dof[it] + bo + 3*PLANE_B,   Blo_g + offB[it] + ko);
            }
            CP_COMMIT();
            CP_WAIT1();
        } else {
            CP_WAIT0();
        }
        __syncthreads();

        const char* base = smc + cur * STG_B;
        const __nv_bfloat16* Ahb = (const __nv_bfloat16*)(base);
        const __nv_bfloat16* Alb = (const __nv_bfloat16*)(base + PLANE_B);
        const __nv_bfloat16* Bhb = (const __nv_bfloat16*)(base + 2*PLANE_B);
        const __nv_bfloat16* Blb = (const __nv_bfloat16*)(base + 3*PLANE_B);

        #pragma unroll
        for (int kk = 0; kk < 2; kk++) {
            const int k0 = kk * 16 + 2 * tq;
            uint32_t ah[4][4], al[4][4], bh[4][2], bl[4][2];
            #pragma unroll
            for (int mi = 0; mi < 4; mi++) {
                const int rw = (aRow0 + mi * 16) * PADB;
                ah[mi][0] = *(const uint32_t*)&Ahb[rw + k0];
                ah[mi][1] = *(const uint32_t*)&Ahb[rw + 8*PADB + k0];
                ah[mi][2] = *(const uint32_t*)&Ahb[rw + k0 + 8];
                ah[mi][3] = *(const uint32_t*)&Ahb[rw + 8*PADB + k0 + 8];
                al[mi][0] = *(const uint32_t*)&Alb[rw + k0];
                al[mi][1] = *(const uint32_t*)&Alb[rw + 8*PADB + k0];
                al[mi][2] = *(const uint32_t*)&Alb[rw + k0 + 8];
                al[mi][3] = *(const uint32_t*)&Alb[rw + 8*PADB + k0 + 8];
            }
            #pragma unroll
            for (int ni = 0; ni < 4; ni++) {
                const int rw = (bRow0 + ni * 8) * PADB;
                bh[ni][0] = *(const uint32_t*)&Bhb[rw + k0];
                bh[ni][1] = *(const uint32_t*)&Bhb[rw + k0 + 8];
                bl[ni][0] = *(const uint32_t*)&Blb[rw + k0];
                bl[ni][1] = *(const uint32_t*)&Blb[rw + k0 + 8];
            }
            #pragma unroll
            for (int mi = 0; mi < 4; mi++)
                #pragma unroll
                for (int ni = 0; ni < 4; ni++) {
                    mma_bf16_16x8x16(acc[mi][ni], al[mi], bh[ni][0], bh[ni][1]);
                    mma_bf16_16x8x16(acc[mi][ni], ah[mi], bl[ni][0], bl[ni][1]);
                    mma_bf16_16x8x16(acc[mi][ni], ah[mi], bh[ni][0], bh[ni][1]);
                }
        }
        __syncthreads();
    }
}

// ===========================================================================
// QKV projection; epilogue writes tf32 hi/lo Q/K/V (K pre-scaled by 1/8)
// ===========================================================================
__global__ __launch_bounds__(256)
void qkv_mma(const float* __restrict__ bq, const float* __restrict__ bk,
             const float* __restrict__ bv)
{
    const float* bias;
    float *ohi, *olo;
    float scale;
    if (blockIdx.z == 0)      { bias = bq; ohi = g_qhi; olo = g_qlo; scale = 1.0f;   }
    else if (blockIdx.z == 1) { bias = bk; ohi = g_khi; olo = g_klo; scale = 0.125f; }
    else                      { bias = bv; ohi = g_vhi; olo = g_vlo; scale = 1.0f;   }

    float acc[4][4][4];
    #pragma unroll
    for (int mi = 0; mi < 4; mi++)
        #pragma unroll
        for (int ni = 0; ni < 4; ni++)
            #pragma unroll
            for (int j = 0; j < 4; j++) acc[mi][ni][j] = 0.f;

    const int row0 = blockIdx.y * 128;
    const int col0 = blockIdx.x * 128;
    gemm_bf16_tile(g_xhi, g_xlo, g_whi[blockIdx.z], g_wlo[blockIdx.z],
                   row0, col0, acc);

    const int tid  = threadIdx.x;
    const int wid  = tid >> 5, lane = tid & 31;
    const int warpM = wid >> 2, warpN = wid & 3;
    const int quad = lane >> 2, tq = lane & 3;

    #pragma unroll
    for (int mi = 0; mi < 4; mi++) {
        #pragma unroll
        for (int half = 0; half < 2; half++) {
            const int r = row0 + warpM * 64 + mi * 16 + quad + half * 8;
            const int b = r >> 11;
            const int sq = r & 2047;
            #pragma unroll
            for (int ni = 0; ni < 4; ni++) {
                const int c  = col0 + warpN * 32 + ni * 8 + 2 * tq;
                const int h  = c >> 6;
                const int hd = c & 63;
                float2 bb = *(const float2*)&bias[c];
                float vx = (acc[mi][ni][half*2+0] + bb.x) * scale;
                float vy = (acc[mi][ni][half*2+1] + bb.y) * scale;
                float hx = __uint_as_float(f2tf32(vx));
                float hy = __uint_as_float(f2tf32(vy));
                float lx = __uint_as_float(f2tf32(vx - hx));
                float ly = __uint_as_float(f2tf32(vy - hy));
                const size_t o = (((size_t)(b * Hn + h) * Seq + sq) * Hd + hd);
                *(float2*)(ohi + o) = make_float2(hx, hy);
                *(float2*)(olo + o) = make_float2(lx, ly);
            }
        }
    }
}

// ===========================================================================
// Output projection: out = att @ Wo^T + bo + comp (att pre-split bf16)
// ===========================================================================
__global__ __launch_bounds__(256)
void proj_mma(const float* __restrict__ bo, const float* __restrict__ comp,
              float* __restrict__ out)
{
    float acc[4][4][4];
    #pragma unroll
    for (int mi = 0; mi < 4; mi++)
        #pragma unroll
        for (int ni = 0; ni < 4; ni++)
            #pragma unroll
            for (int j = 0; j < 4; j++) acc[mi][ni][j] = 0.f;

    const int row0 = blockIdx.y * 128;
    const int col0 = blockIdx.x * 128;
    gemm_bf16_tile(g_ahi, g_alo, g_whi[3], g_wlo[3], row0, col0, acc);

    const int tid  = threadIdx.x;
    const int wid  = tid >> 5, lane = tid & 31;
    const int warpM = wid >> 2, warpN = wid & 3;
    const int quad = lane >> 2, tq = lane & 3;

    #pragma unroll
    for (int mi = 0; mi < 4; mi++) {
        #pragma unroll
        for (int half = 0; half < 2; half++) {
            const int r = row0 + warpM * 64 + mi * 16 + quad + half * 8;
            #pragma unroll
            for (int ni = 0; ni < 4; ni++) {
                const int c = col0 + warpN * 32 + ni * 8 + 2 * tq;
                float2 bb = *(const float2*)&bo[c];
                float2 cc = *(const float2*)&comp[c];
                float2 v;
                v.x = acc[mi][ni][half * 2 + 0] + bb.x + cc.x;
                v.y = acc[mi][ni][half * 2 + 1] + bb.y + cc.y;
                *(float2*)(out + (size_t)r * Dm + c) = v;
            }
        }
    }
}

// ===========================================================================
// Flash attention, 3xTF32 on pre-split Q/K/V (proven R8). BM=128, BN=64.
// Epilogue now writes bf16 hi/lo planes for proj.
// ===========================================================================
#define PQ   68
#define PVV  72
#define QSB_F  (128*PQ)
#define KS_F   (64*PQ)
#define VS_F   (64*PVV)
#define FSTG_F (2*KS_F + 2*VS_F)
#define FLASH_SMEM_BYTES ((QSB_F + 2*FSTG_F)*4)   // 178176 B

__global__ __launch_bounds__(256)
void flash_mma()
{
    const int qt = blockIdx.x;           // 0..15
    const int bh = blockIdx.y;           // 0..63
    const size_t bho = (size_t)bh * Seq * Hd;

    extern __shared__ float fs[];
    float* Qs = fs;                      // reused as Ps
    float* stage0 = fs + QSB_F;

    const int tid  = threadIdx.x;
    const int wid  = tid >> 5, lane = tid & 31;
    const int quad = lane >> 2, tq = lane & 3;
    const int r0   = wid * 16;

    uint32_t kdo[4], vdo[4];
    size_t srco[4];
    #pragma unroll
    for (int i = 0; i < 4; i++) {
        int id = i * 256 + tid;
        int row = id >> 4, seg = id & 15;
        kdo[i]  = (uint32_t)(row * PQ  + seg * 4) * 4u;
        vdo[i]  = (uint32_t)(row * PVV + seg * 4) * 4u;
        srco[i] = (size_t)row * Hd + seg * 4;
    }
    const uint32_t qsb = smem_u32(Qs);
    const uint32_t st0 = smem_u32(stage0);
    const uint32_t KSB = KS_F * 4u, VSB = VS_F * 4u;
    const uint32_t stgB = FSTG_F * 4u;

    #pragma unroll
    for (int i = 0; i < 8; i++) {
        int id = i * 256 + tid;
        int row = id >> 4, seg = id & 15;
        CP16(qsb + (uint32_t)(row*PQ + seg*4)*4u,
             g_qhi + bho + (size_t)(qt*128 + row) * Hd + seg*4);
    }
    #pragma unroll
    for (int i = 0; i < 4; i++) {
        CP16(st0 + kdo[i],               g_khi + bho + srco[i]);
        CP16(st0 + KSB + kdo[i],         g_klo + bho + srco[i]);
        CP16(st0 + 2*KSB + vdo[i],       g_vhi + bho + srco[i]);
        CP16(st0 + 2*KSB + VSB + vdo[i], g_vlo + bho + srco[i]);
    }
    CP_COMMIT();
    CP_WAIT0();
    __syncthreads();

    uint32_t qhi[8][4], qlo[8][4];
    #pragma unroll
    for (int kk = 0; kk < 8; kk++) {
        const int k0 = kk * 8 + tq;
        qhi[kk][0] = fau(Qs[(r0 + quad)     * PQ + k0]);
        qhi[kk][1] = fau(Qs[(r0 + quad + 8) * PQ + k0]);
        qhi[kk][2] = fau(Qs[(r0 + quad)     * PQ + k0 + 4]);
        qhi[kk][3] = fau(Qs[(r0 + quad + 8) * PQ + k0 + 4]);
    }
    __syncthreads();

    #pragma unroll
    for (int i = 0; i < 8; i++) {
        int id = i * 256 + tid;
        int row = id >> 4, seg = id & 15;
        CP16(qsb + (uint32_t)(row*PQ + seg*4)*4u,
             g_qlo + bho + (size_t)(qt*128 + row) * Hd + seg*4);
    }
    CP_COMMIT();
    CP_WAIT0();
    __syncthreads();
    #pragma unroll
    for (int kk = 0; kk < 8; kk++) {
        const int k0 = kk * 8 + tq;
        qlo[kk][0] = fau(Qs[(r0 + quad)     * PQ + k0]);
        qlo[kk][1] = fau(Qs[(r0 + quad + 8) * PQ + k0]);
        qlo[kk][2] = fau(Qs[(r0 + quad)     * PQ + k0 + 4]);
        qlo[kk][3] = fau(Qs[(r0 + quad + 8) * PQ + k0 + 4]);
    }
    float* Ps = Qs;

    float m_i[2] = { -1e30f, -1e30f };
    float l_i[2] = { 0.f, 0.f };
    float oacc[8][4];
    #pragma unroll
    for (int ni = 0; ni < 8; ni++)
        #pragma unroll
        for (int j = 0; j < 4; j++) oacc[ni][j] = 0.f;

    const int jend = 2 * qt + 1;
    const int ig0  = qt * 128 + r0 + quad;

    for (int jt = 0; jt <= jend; jt++) {
        __syncthreads();

        const int cur = jt & 1;
        if (jt + 1 <= jend) {
            const uint32_t sb = st0 + (uint32_t)((jt + 1) & 1) * stgB;
            const size_t ro = (size_t)((jt + 1) * 64) * Hd;
            #pragma unroll
            for (int i = 0; i < 4; i++) {
                CP16(sb + kdo[i],               g_khi + bho + ro + srco[i]);
                CP16(sb + KSB + kdo[i],         g_klo + bho + ro + srco[i]);
                CP16(sb + 2*KSB + vdo[i],       g_vhi + bho + ro + srco[i]);
                CP16(sb + 2*KSB + VSB + vdo[i], g_vlo + bho + ro + srco[i]);
            }
            CP_COMMIT();
            CP_WAIT1();
        } else {
            CP_WAIT0();
        }
        __syncthreads();

        const float* base = stage0 + cur * FSTG_F;
        const float* Khi = base;
        const float* Klo = base + KS_F;
        const float* Vhi = base + 2 * KS_F;
        const float* Vlo = base + 2 * KS_F + VS_F;

        float sacc[8][4];
        #pragma unroll
        for (int ni = 0; ni < 8; ni++)
            #pragma unroll
            for (int j = 0; j < 4; j++) sacc[ni][j] = 0.f;

        #pragma unroll
        for (int ni = 0; ni < 8; ni++) {
            const float* kh = Khi + (ni * 8 + quad) * PQ;
            const float* kl = Klo + (ni * 8 + quad) * PQ;
            #pragma unroll
            for (int kk = 0; kk < 8; kk++) {
                const int k0 = kk * 8 + tq;
                uint32_t bh0 = fau(kh[k0]), bh1 = fau(kh[k0 + 4]);
                uint32_t bl0 = fau(kl[k0]), bl1 = fau(kl[k0 + 4]);
                mma_tf32_16x8x8(sacc[ni], qlo[kk], bh0, bh1);
                mma_tf32_16x8x8(sacc[ni], qhi[kk], bl0, bl1);
                mma_tf32_16x8x8(sacc[ni], qhi[kk], bh0, bh1);
            }
        }

        if (jt >= 2 * qt) {
            const int jg0 = jt * 64;
            #pragma unroll
            for (int ni = 0; ni < 8; ni++) {
                const int jg = jg0 + ni * 8 + 2 * tq;
                if (jg     > ig0)      sacc[ni][0] = -1e30f;
                if (jg + 1 > ig0)      sacc[ni][1] = -1e30f;
                if (jg     > ig0 + 8)  sacc[ni][2] = -1e30f;
                if (jg + 1 > ig0 + 8)  sacc[ni][3] = -1e30f;
            }
        }

        float mloc0 = -1e30f, mloc1 = -1e30f;
        #pragma unroll
        for (int ni = 0; ni < 8; ni++) {
            mloc0 = fmaxf(mloc0, fmaxf(sacc[ni][0], sacc[ni][1]));
            mloc1 = fmaxf(mloc1, fmaxf(sacc[ni][2], sacc[ni][3]));
        }
        #pragma unroll
        for (int off = 1; off < 4; off <<= 1) {
            mloc0 = fmaxf(mloc0, __shfl_xor_sync(0xffffffffu, mloc0, off));
            mloc1 = fmaxf(mloc1, __shfl_xor_sync(0xffffffffu, mloc1, off));
        }
        const float mnew0 = fmaxf(m_i[0], mloc0);
        const float mnew1 = fmaxf(m_i[1], mloc1);
        const float al0 = __expf(m_i[0] - mnew0);
        const float al1 = __expf(m_i[1] - mnew1);
        float ps0 = 0.f, ps1 = 0.f;
        #pragma unroll
        for (int ni = 0; ni < 8; ni++) {
            sacc[ni][0] = __expf(sacc[ni][0] - mnew0);
            sacc[ni][1] = __expf(sacc[ni][1] - mnew0);
            sacc[ni][2] = __expf(sacc[ni][2] - mnew1);
            sacc[ni][3] = __expf(sacc[ni][3] - mnew1);
            ps0 += sacc[ni][0] + sacc[ni][1];
            ps1 += sacc[ni][2] + sacc[ni][3];
        }
        #pragma unroll
        for (int off = 1; off < 4; off <<= 1) {
            ps0 += __shfl_xor_sync(0xffffffffu, ps0, off);
            ps1 += __shfl_xor_sync(0xffffffffu, ps1, off);
        }
        l_i[0] = l_i[0] * al0 + ps0;  m_i[0] = mnew0;
        l_i[1] = l_i[1] * al1 + ps1;  m_i[1] = mnew1;
        #pragma unroll
        for (int ni = 0; ni < 8; ni++) {
            oacc[ni][0] *= al0; oacc[ni][1] *= al0;
            oacc[ni][2] *= al1; oacc[ni][3] *= al1;
        }

        #pragma unroll
        for (int ni = 0; ni < 8; ni++) {
            *(float2*)&Ps[(r0 + quad)     * PQ + ni * 8 + 2 * tq] =
                make_float2(sacc[ni][0], sacc[ni][1]);
            *(float2*)&Ps[(r0 + quad + 8) * PQ + ni * 8 + 2 * tq] =
                make_float2(sacc[ni][2], sacc[ni][3]);
        }
        __syncwarp();

        #pragma unroll
        for (int kk = 0; kk < 8; kk++) {
            const int k0 = kk * 8 + tq;
            float p0 = Ps[(r0 + quad)     * PQ + k0];
            float p1 = Ps[(r0 + quad + 8) * PQ + k0];
            float p2 = Ps[(r0 + quad)     * PQ + k0 + 4];
            float p3 = Ps[(r0 + quad + 8) * PQ + k0 + 4];
            uint32_t ph[4], pl[4];
            ph[0] = f2tf32(p0); pl[0] = f2tf32(p0 - __uint_as_float(ph[0]));
            ph[1] = f2tf32(p1); pl[1] = f2tf32(p1 - __uint_as_float(ph[1]));
            ph[2] = f2tf32(p2); pl[2] = f2tf32(p2 - __uint_as_float(ph[2]));
            ph[3] = f2tf32(p3); pl[3] = f2tf32(p3 - __uint_as_float(ph[3]));
            const float* vh0 = Vhi + (kk * 8 + tq) * PVV;
            const float* vh1 = Vhi + (kk * 8 + tq + 4) * PVV;
            const float* vl0 = Vlo + (kk * 8 + tq) * PVV;
            const float* vl1 = Vlo + (kk * 8 + tq + 4) * PVV;
            #pragma unroll
            for (int ni = 0; ni < 8; ni++) {
                uint32_t bh0 = fau(vh0[ni * 8 + quad]);
                uint32_t bh1 = fau(vh1[ni * 8 + quad]);
                uint32_t bl0 = fau(vl0[ni * 8 + quad]);
                uint32_t bl1 = fau(vl1[ni * 8 + quad]);
                mma_tf32_16x8x8(oacc[ni], pl, bh0, bh1);
                mma_tf32_16x8x8(oacc[ni], ph, bl0, bl1);
                mma_tf32_16x8x8(oacc[ni], ph, bh0, bh1);
            }
        }
        __syncwarp();
    }

    // ---- normalize + write bf16 hi/lo att to [B,S,H,HD] ----
    const int bidx = bh >> 4, h = bh & 15;
    #pragma unroll
    for (int half = 0; half < 2; half++) {
        const float inv = 1.0f / l_i[half];
        const int s = qt * 128 + r0 + quad + half * 8;
        const size_t dof = ((size_t)bidx * Seq + s) * Hn * Hd + (size_t)h * Hd;
        #pragma unroll
        for (int ni = 0; ni < 8; ni++) {
            float vx = oacc[ni][half * 2 + 0] * inv;
            float vy = oacc[ni][half * 2 + 1] * inv;
            __nv_bfloat16 hx = __float2bfloat16_rn(vx);
            __nv_bfloat16 hy = __float2bfloat16_rn(vy);
            __nv_bfloat16 lx = __float2bfloat16_rn(vx - __bfloat162float(hx));
            __nv_bfloat16 ly = __float2bfloat16_rn(vy - __bfloat162float(hy));
            __nv_bfloat162 hp = {hx, hy}, lp = {lx, ly};
            *(uint32_t*)&g_ahi[dof + ni * 8 + 2 * tq] = *(uint32_t*)&hp;
            *(uint32_t*)&g_alo[dof + ni * 8 + 2 * tq] = *(uint32_t*)&lp;
        }
    }
}

// ---------------------------------------------------------------------------
extern "C" void kernel_launch(void* const* d_in, const int* in_sizes, int n_in,
                              void* d_out, int out_size)
{
    (void)in_sizes; (void)n_in; (void)out_size;
    const float* X    = (const float*)d_in[0];
    const float* Wq   = (const float*)d_in[1];
    const float* bq   = (const float*)d_in[2];
    const float* Wk   = (const float*)d_in[3];
    const float* bk   = (const float*)d_in[4];
    const float* Wv   = (const float*)d_in[5];
    const float* bv   = (const float*)d_in[6];
    const float* Wo   = (const float*)d_in[7];
    const float* bo   = (const float*)d_in[8];
    const float* comp = (const float*)d_in[9];
    float* out = (float*)d_out;

    cudaFuncSetAttribute(qkv_mma,   cudaFuncAttributeMaxDynamicSharedMemorySize, GEMM_SMEM_BYTES);
    cudaFuncSetAttribute(proj_mma,  cudaFuncAttributeMaxDynamicSharedMemorySize, GEMM_SMEM_BYTES);
    cudaFuncSetAttribute(flash_mma, cudaFuncAttributeMaxDynamicSharedMemorySize, FLASH_SMEM_BYTES);

    dim3 gS(512, 5);                     // split X + 4 W's
    split_xw<<<gS, 256>>>(X, Wq, Wk, Wv, Wo);

    dim3 gQKV(Dm/128, Mrows/128, 3);     // (8, 64, 3)
    qkv_mma<<<gQKV, 256, GEMM_SMEM_BYTES>>>(bq, bk, bv);

    dim3 gFA(Seq/128, Bsz*Hn);           // (16, 64)
    flash_mma<<<gFA, 256, FLASH_SMEM_BYTES>>>();

    dim3 gP(Dm/128, Mrows/128);          // (8, 64)
    proj_mma<<<gP, 256, GEMM_SMEM_BYTES>>>(bo, comp, out);
}

// round 12
// speedup vs baseline: 2.3990x; 1.2647x over previous
#include <cuda_runtime.h>
#include <cuda_bf16.h>
#include <cstdint>

#define Bsz 4
#define Seq 2048
#define Dm  1024
#define Hn  16
#define Hd  64
#define Mrows (Bsz*Seq)   // 8192

// Scratch (allocation-free rule: __device__ globals)
// bf16 hi/lo planes, dense GEMM operands:
__device__ __nv_bfloat16 g_xhi[Mrows*Dm],  g_xlo[Mrows*Dm];
__device__ __nv_bfloat16 g_whi[4][Dm*Dm],  g_wlo[4][Dm*Dm];
__device__ __nv_bfloat16 g_ahi[Bsz*Seq*Dm], g_alo[Bsz*Seq*Dm];
// bf16 hi/lo planes for flash:
__device__ __nv_bfloat16 g_qhi[Bsz*Hn*Seq*Hd], g_qlo[Bsz*Hn*Seq*Hd];  // [B,H,S,HD], pre-scaled 1/8
__device__ __nv_bfloat16 g_khi[Bsz*Hn*Seq*Hd], g_klo[Bsz*Hn*Seq*Hd];  // [B,H,S,HD]
__device__ __nv_bfloat16 g_vthi[Bsz*Hn*Hd*Seq], g_vtlo[Bsz*Hn*Hd*Seq]; // [B,H,HD,S] transposed

// ===========================================================================
// Common helpers
// ===========================================================================
__device__ __forceinline__ uint32_t smem_u32(const void* p) {
    uint32_t a;
    asm("{ .reg .u64 t; cvta.to.shared.u64 t, %1; cvt.u32.u64 %0, t; }"
        : "=r"(a) : "l"(p));
    return a;
}

#define CP16(dst, src) \
    asm volatile("cp.async.cg.shared.global [%0], [%1], 16;" :: "r"(dst), "l"(src))
#define CP_COMMIT()  asm volatile("cp.async.commit_group;" ::: "memory")
#define CP_WAIT1()   asm volatile("cp.async.wait_group 1;" ::: "memory")
#define CP_WAIT0()   asm volatile("cp.async.wait_group 0;" ::: "memory")

__device__ __forceinline__ void mma_bf16_16x8x16(float c[4], const uint32_t a[4],
                                                 uint32_t b0, uint32_t b1) {
    asm volatile(
        "mma.sync.aligned.m16n8k16.row.col.f32.bf16.bf16.f32 "
        "{%0,%1,%2,%3}, {%4,%5,%6,%7}, {%8,%9}, {%0,%1,%2,%3};"
        : "+f"(c[0]), "+f"(c[1]), "+f"(c[2]), "+f"(c[3])
        : "r"(a[0]), "r"(a[1]), "r"(a[2]), "r"(a[3]), "r"(b0), "r"(b1));
}

// Split pair of fp32 -> packed bf16x2 hi + lo
__device__ __forceinline__ void splitb(float x, float y, uint32_t& hi, uint32_t& lo) {
    __nv_bfloat162 h;
    h.x = __float2bfloat16_rn(x);
    h.y = __float2bfloat16_rn(y);
    __nv_bfloat162 l;
    l.x = __float2bfloat16_rn(x - __bfloat162float(h.x));
    l.y = __float2bfloat16_rn(y - __bfloat162float(h.y));
    hi = *(uint32_t*)&h;
    lo = *(uint32_t*)&l;
}

// ===========================================================================
// Split pre-pass: X and 4 W matrices -> bf16 hi/lo planes
// ===========================================================================
__global__ __launch_bounds__(256)
void split_xw(const float* __restrict__ X,
              const float* __restrict__ Wq, const float* __restrict__ Wk,
              const float* __restrict__ Wv, const float* __restrict__ Wo)
{
    const int z = blockIdx.y;
    const float* src;
    __nv_bfloat16 *dhi, *dlo;
    int n4;
    if (z == 0)      { src = X;  dhi = g_xhi;    dlo = g_xlo;    n4 = Mrows*Dm/4; }
    else if (z == 1) { src = Wq; dhi = g_whi[0]; dlo = g_wlo[0]; n4 = Dm*Dm/4; }
    else if (z == 2) { src = Wk; dhi = g_whi[1]; dlo = g_wlo[1]; n4 = Dm*Dm/4; }
    else if (z == 3) { src = Wv; dhi = g_whi[2]; dlo = g_wlo[2]; n4 = Dm*Dm/4; }
    else             { src = Wo; dhi = g_whi[3]; dlo = g_wlo[3]; n4 = Dm*Dm/4; }

    for (int i = blockIdx.x * blockDim.x + threadIdx.x; i < n4;
         i += gridDim.x * blockDim.x) {
        float4 v = ((const float4*)src)[i];
        uint32_t h0, l0, h1, l1;
        splitb(v.x, v.y, h0, l0);
        splitb(v.z, v.w, h1, l1);
        *(uint2*)&dhi[4*i] = make_uint2(h0, h1);
        *(uint2*)&dlo[4*i] = make_uint2(l0, l1);
    }
}

// ===========================================================================
// 3xBF16 GEMM on pre-split bf16 planes (proven R9). C[128x128], K=1024.
// ===========================================================================
#define KTB   32
#define PADB  40
#define PLANE_B (128*PADB*2)          // 10240 bytes per plane
#define STG_B   (4*PLANE_B)
#define GEMM_SMEM_BYTES (2*STG_B)     // 81920

__device__ __forceinline__ void gemm_bf16_tile(const __nv_bfloat16* __restrict__ Ahi_g,
                                               const __nv_bfloat16* __restrict__ Alo_g,
                                               const __nv_bfloat16* __restrict__ Bhi_g,
                                               const __nv_bfloat16* __restrict__ Blo_g,
                                               int row0, int col0,
                                               float acc[4][4][4])
{
    extern __shared__ char smc[];
    const int tid  = threadIdx.x;
    const int wid  = tid >> 5, lane = tid & 31;
    const int warpM = wid >> 2, warpN = wid & 3;
    const int quad = lane >> 2, tq = lane & 3;

    uint32_t dof[2];
    size_t offA[2], offB[2];
    const uint32_t smb = smem_u32(smc);
    #pragma unroll
    for (int it = 0; it < 2; it++) {
        int id = it * 256 + tid;
        int r  = id >> 2;
        int c  = id & 3;
        dof[it]  = smb + (uint32_t)(r * 80 + c * 16);
        offA[it] = (size_t)(row0 + r) * Dm + c * 8;
        offB[it] = (size_t)(col0 + r) * Dm + c * 8;
    }

    const int aRow0 = warpM * 64 + quad;
    const int bRow0 = warpN * 32 + quad;

    #pragma unroll
    for (int it = 0; it < 2; it++) {
        CP16(dof[it],               Ahi_g + offA[it]);
        CP16(dof[it] +   PLANE_B,   Alo_g + offA[it]);
        CP16(dof[it] + 2*PLANE_B,   Bhi_g + offB[it]);
        CP16(dof[it] + 3*PLANE_B,   Blo_g + offB[it]);
    }
    CP_COMMIT();

    const int NST = Dm / KTB;
    for (int s = 0; s < NST; s++) {
        const int cur = s & 1;
        if (s + 1 < NST) {
            const uint32_t bo = (uint32_t)((s + 1) & 1) * STG_B;
            const int ko = (s + 1) * KTB;
            #pragma unroll
            for (int it = 0; it < 2; it++) {
                CP16(dof[it] + bo,               Ahi_g + offA[it] + ko);
                CP16(dof[it] + bo +   PLANE_B,   Alo_g + offA[it] + ko);
                CP16(dof[it] + bo + 2*PLANE_B,   Bhi_g + offB[it] + ko);
                CP16(dof[it] + bo + 3*PLANE_B,   Blo_g + offB[it] + ko);
            }
            CP_COMMIT();
            CP_WAIT1();
        } else {
            CP_WAIT0();
        }
        __syncthreads();

        const char* base = smc + cur * STG_B;
        const __nv_bfloat16* Ahb = (const __nv_bfloat16*)(base);
        const __nv_bfloat16* Alb = (const __nv_bfloat16*)(base + PLANE_B);
        const __nv_bfloat16* Bhb = (const __nv_bfloat16*)(base + 2*PLANE_B);
        const __nv_bfloat16* Blb = (const __nv_bfloat16*)(base + 3*PLANE_B);

        #pragma unroll
        for (int kk = 0; kk < 2; kk++) {
            const int k0 = kk * 16 + 2 * tq;
            uint32_t ah[4][4], al[4][4], bh[4][2], bl[4][2];
            #pragma unroll
            for (int mi = 0; mi < 4; mi++) {
                const int rw = (aRow0 + mi * 16) * PADB;
                ah[mi][0] = *(const uint32_t*)&Ahb[rw + k0];
                ah[mi][1] = *(const uint32_t*)&Ahb[rw + 8*PADB + k0];
                ah[mi][2] = *(const uint32_t*)&Ahb[rw + k0 + 8];
                ah[mi][3] = *(const uint32_t*)&Ahb[rw + 8*PADB + k0 + 8];
                al[mi][0] = *(const uint32_t*)&Alb[rw + k0];
                al[mi][1] = *(const uint32_t*)&Alb[rw + 8*PADB + k0];
                al[mi][2] = *(const uint32_t*)&Alb[rw + k0 + 8];
                al[mi][3] = *(const uint32_t*)&Alb[rw + 8*PADB + k0 + 8];
            }
            #pragma unroll
            for (int ni = 0; ni < 4; ni++) {
                const int rw = (bRow0 + ni * 8) * PADB;
                bh[ni][0] = *(const uint32_t*)&Bhb[rw + k0];
                bh[ni][1] = *(const uint32_t*)&Bhb[rw + k0 + 8];
                bl[ni][0] = *(const uint32_t*)&Blb[rw + k0];
                bl[ni][1] = *(const uint32_t*)&Blb[rw + k0 + 8];
            }
            #pragma unroll
            for (int mi = 0; mi < 4; mi++)
                #pragma unroll
                for (int ni = 0; ni < 4; ni++) {
                    mma_bf16_16x8x16(acc[mi][ni], al[mi], bh[ni][0], bh[ni][1]);
                    mma_bf16_16x8x16(acc[mi][ni], ah[mi], bl[ni][0], bl[ni][1]);
                    mma_bf16_16x8x16(acc[mi][ni], ah[mi], bh[ni][0], bh[ni][1]);
                }
        }
        __syncthreads();
    }
}

// ===========================================================================
// QKV projection; epilogue writes bf16 hi/lo planes.
// Q pre-scaled 1/8; V written TRANSPOSED [B,H,HD,S].
// ===========================================================================
__global__ __launch_bounds__(256)
void qkv_mma(const float* __restrict__ bq, const float* __restrict__ bk,
             const float* __restrict__ bv)
{
    const int z = blockIdx.z;
    const float* bias = (z == 0) ? bq : (z == 1) ? bk : bv;
    const float scale = (z == 0) ? 0.125f : 1.0f;

    float acc[4][4][4];
    #pragma unroll
    for (int mi = 0; mi < 4; mi++)
        #pragma unroll
        for (int ni = 0; ni < 4; ni++)
            #pragma unroll
            for (int j = 0; j < 4; j++) acc[mi][ni][j] = 0.f;

    const int row0 = blockIdx.y * 128;
    const int col0 = blockIdx.x * 128;
    gemm_bf16_tile(g_xhi, g_xlo, g_whi[z], g_wlo[z], row0, col0, acc);

    const int tid  = threadIdx.x;
    const int wid  = tid >> 5, lane = tid & 31;
    const int warpM = wid >> 2, warpN = wid & 3;
    const int quad = lane >> 2, tq = lane & 3;

    #pragma unroll
    for (int mi = 0; mi < 4; mi++) {
        #pragma unroll
        for (int half = 0; half < 2; half++) {
            const int r = row0 + warpM * 64 + mi * 16 + quad + half * 8;
            const int b = r >> 11;
            const int sq = r & 2047;
            #pragma unroll
            for (int ni = 0; ni < 4; ni++) {
                const int c  = col0 + warpN * 32 + ni * 8 + 2 * tq;
                const int h  = c >> 6;
                const int hd = c & 63;
                float2 bb = *(const float2*)&bias[c];
                float vx = (acc[mi][ni][half*2+0] + bb.x) * scale;
                float vy = (acc[mi][ni][half*2+1] + bb.y) * scale;
                uint32_t hp, lp;
                splitb(vx, vy, hp, lp);
                if (z == 2) {
                    // V transposed: [B,H,HD,S]
                    const size_t ot = ((size_t)(b * Hn + h) * Hd + hd) * Seq + sq;
                    __nv_bfloat162 h2 = *(__nv_bfloat162*)&hp;
                    __nv_bfloat162 l2 = *(__nv_bfloat162*)&lp;
                    g_vthi[ot]       = h2.x;  g_vthi[ot + Seq] = h2.y;
                    g_vtlo[ot]       = l2.x;  g_vtlo[ot + Seq] = l2.y;
                } else {
                    const size_t o = (((size_t)(b * Hn + h) * Seq + sq) * Hd + hd);
                    if (z == 0) {
                        *(uint32_t*)&g_qhi[o] = hp;
                        *(uint32_t*)&g_qlo[o] = lp;
                    } else {
                        *(uint32_t*)&g_khi[o] = hp;
                        *(uint32_t*)&g_klo[o] = lp;
                    }
                }
            }
        }
    }
}

// ===========================================================================
// Output projection: out = att @ Wo^T + bo + comp (att pre-split bf16)
// ===========================================================================
__global__ __launch_bounds__(256)
void proj_mma(const float* __restrict__ bo, const float* __restrict__ comp,
              float* __restrict__ out)
{
    float acc[4][4][4];
    #pragma unroll
    for (int mi = 0; mi < 4; mi++)
        #pragma unroll
        for (int ni = 0; ni < 4; ni++)
            #pragma unroll
            for (int j = 0; j < 4; j++) acc[mi][ni][j] = 0.f;

    const int row0 = blockIdx.y * 128;
    const int col0 = blockIdx.x * 128;
    gemm_bf16_tile(g_ahi, g_alo, g_whi[3], g_wlo[3], row0, col0, acc);

    const int tid  = threadIdx.x;
    const int wid  = tid >> 5, lane = tid & 31;
    const int warpM = wid >> 2, warpN = wid & 3;
    const int quad = lane >> 2, tq = lane & 3;

    #pragma unroll
    for (int mi = 0; mi < 4; mi++) {
        #pragma unroll
        for (int half = 0; half < 2; half++) {
            const int r = row0 + warpM * 64 + mi * 16 + quad + half * 8;
            #pragma unroll
            for (int ni = 0; ni < 4; ni++) {
                const int c = col0 + warpN * 32 + ni * 8 + 2 * tq;
                float2 bb = *(const float2*)&bo[c];
                float2 cc = *(const float2*)&comp[c];
                float2 v;
                v.x = acc[mi][ni][half * 2 + 0] + bb.x + cc.x;
                v.y = acc[mi][ni][half * 2 + 1] + bb.y + cc.y;
                *(float2*)(out + (size_t)r * Dm + c) = v;
            }
        }
    }
}

// ===========================================================================
// Flash attention, 3xBF16 m16n8k16. BM=128, BN=64, 256 threads (8 warps).
// K natural [j][d]; V transposed [d][j]; P split to bf16 planes at store.
// Smem rows: 64 bf16 data padded to FPAD=72 (144 B) — conflict-free.
// ===========================================================================
#define FPAD 72
#define FROW 144
#define QP_B  (128*FROW)            // 18432: Q staging, then Phi
#define PLO_B (128*FROW)            // 18432: Plo
#define KPLANE (64*FROW)            // 9216
#define FSTGB  (4*KPLANE)           // 36864: Khi|Klo|VThi|VTlo
#define FLASH_SMEM_BYTES (QP_B + PLO_B + 2*FSTGB)   // 110592

__global__ __launch_bounds__(256)
void flash_mma()
{
    const int qt = blockIdx.x;           // 0..15
    const int bh = blockIdx.y;           // 0..63
    const size_t bho = (size_t)bh * Seq * Hd;    // K/Q base
    const size_t bhv = (size_t)bh * Hd * Seq;    // VT base

    extern __shared__ char fsm[];
    const uint32_t qpb  = smem_u32(fsm);         // Q staging / Phi
    const uint32_t plob = qpb + QP_B;            // Plo
    const uint32_t st0  = qpb + QP_B + PLO_B;    // stage 0

    const int tid  = threadIdx.x;
    const int wid  = tid >> 5, lane = tid & 31;
    const int quad = lane >> 2, tq = lane & 3;
    const int r0   = wid * 16;

    // K/VT cp.async slots: 512 chunks per plane, 2/thread
    uint32_t koff[2];
    size_t ksrc[2], vsrc[2];
    #pragma unroll
    for (int i = 0; i < 2; i++) {
        int id = i * 256 + tid;
        int row = id >> 3, c = id & 7;
        koff[i] = (uint32_t)(row * FROW + c * 16);
        ksrc[i] = (size_t)row * Hd + c * 8;
        vsrc[i] = (size_t)row * Seq + c * 8;
    }

    // ---- Prologue: Qhi + stage 0, then Qlo ----
    #pragma unroll
    for (int i = 0; i < 4; i++) {
        int id = i * 256 + tid;
        int row = id >> 3, c = id & 7;
        CP16(qpb + (uint32_t)(row * FROW + c * 16),
             g_qhi + bho + (size_t)(qt * 128 + row) * Hd + c * 8);
    }
    #pragma unroll
    for (int i = 0; i < 2; i++) {
        CP16(st0 + koff[i],              g_khi  + bho + ksrc[i]);
        CP16(st0 + KPLANE + koff[i],     g_klo  + bho + ksrc[i]);
        CP16(st0 + 2*KPLANE + koff[i],   g_vthi + bhv + vsrc[i]);
        CP16(st0 + 3*KPLANE + koff[i],   g_vtlo + bhv + vsrc[i]);
    }
    CP_COMMIT();
    CP_WAIT0();
    __syncthreads();

    const __nv_bfloat16* QPb = (const __nv_bfloat16*)fsm;
    uint32_t qhi[4][4], qlo[4][4];
    #pragma unroll
    for (int kk = 0; kk < 4; kk++) {
        const int k0 = kk * 16 + 2 * tq;
        const int rw0 = (r0 + quad) * FPAD;
        qhi[kk][0] = *(const uint32_t*)&QPb[rw0 + k0];
        qhi[kk][1] = *(const uint32_t*)&QPb[rw0 + 8*FPAD + k0];
        qhi[kk][2] = *(const uint32_t*)&QPb[rw0 + k0 + 8];
        qhi[kk][3] = *(const uint32_t*)&QPb[rw0 + 8*FPAD + k0 + 8];
    }
    __syncthreads();
    #pragma unroll
    for (int i = 0; i < 4; i++) {
        int id = i * 256 + tid;
        int row = id >> 3, c = id & 7;
        CP16(qpb + (uint32_t)(row * FROW + c * 16),
             g_qlo + bho + (size_t)(qt * 128 + row) * Hd + c * 8);
    }
    CP_COMMIT();
    CP_WAIT0();
    __syncthreads();
    #pragma unroll
    for (int kk = 0; kk < 4; kk++) {
        const int k0 = kk * 16 + 2 * tq;
        const int rw0 = (r0 + quad) * FPAD;
        qlo[kk][0] = *(const uint32_t*)&QPb[rw0 + k0];
        qlo[kk][1] = *(const uint32_t*)&QPb[rw0 + 8*FPAD + k0];
        qlo[kk][2] = *(const uint32_t*)&QPb[rw0 + k0 + 8];
        qlo[kk][3] = *(const uint32_t*)&QPb[rw0 + 8*FPAD + k0 + 8];
    }
    __syncthreads();   // Q staging now free -> Phi

    float m_i[2] = { -1e30f, -1e30f };
    float l_i[2] = { 0.f, 0.f };
    float oacc[8][4];
    #pragma unroll
    for (int ni = 0; ni < 8; ni++)
        #pragma unroll
        for (int j = 0; j < 4; j++) oacc[ni][j] = 0.f;

    const int jend = 2 * qt + 1;
    const int ig0  = qt * 128 + r0 + quad;

    for (int jt = 0; jt <= jend; jt++) {
        __syncthreads();

        const int cur = jt & 1;
        if (jt + 1 <= jend) {
            const uint32_t sb = st0 + (uint32_t)((jt + 1) & 1) * FSTGB;
            const size_t kro = (size_t)((jt + 1) * 64) * Hd;
            const size_t vro = (size_t)((jt + 1) * 64);
            #pragma unroll
            for (int i = 0; i < 2; i++) {
                CP16(sb + koff[i],              g_khi  + bho + kro + ksrc[i]);
                CP16(sb + KPLANE + koff[i],     g_klo  + bho + kro + ksrc[i]);
                CP16(sb + 2*KPLANE + koff[i],   g_vthi + bhv + vro + vsrc[i]);
                CP16(sb + 3*KPLANE + koff[i],   g_vtlo + bhv + vro + vsrc[i]);
            }
            CP_COMMIT();
            CP_WAIT1();
        } else {
            CP_WAIT0();
        }
        __syncthreads();

        const char* base = fsm + QP_B + PLO_B + cur * FSTGB;
        const __nv_bfloat16* Khi  = (const __nv_bfloat16*)(base);
        const __nv_bfloat16* Klo  = (const __nv_bfloat16*)(base + KPLANE);
        const __nv_bfloat16* VThi = (const __nv_bfloat16*)(base + 2*KPLANE);
        const __nv_bfloat16* VTlo = (const __nv_bfloat16*)(base + 3*KPLANE);

        // ---- S = Q K^T (3xBF16) ----
        float sacc[8][4];
        #pragma unroll
        for (int ni = 0; ni < 8; ni++)
            #pragma unroll
            for (int j = 0; j < 4; j++) sacc[ni][j] = 0.f;

        #pragma unroll
        for (int ni = 0; ni < 8; ni++) {
            const int rw = (ni * 8 + quad) * FPAD;
            #pragma unroll
            for (int kk = 0; kk < 4; kk++) {
                const int k0 = kk * 16 + 2 * tq;
                uint32_t bh0 = *(const uint32_t*)&Khi[rw + k0];
                uint32_t bh1 = *(const uint32_t*)&Khi[rw + k0 + 8];
                uint32_t bl0 = *(const uint32_t*)&Klo[rw + k0];
                uint32_t bl1 = *(const uint32_t*)&Klo[rw + k0 + 8];
                mma_bf16_16x8x16(sacc[ni], qlo[kk], bh0, bh1);
                mma_bf16_16x8x16(sacc[ni], qhi[kk], bl0, bl1);
                mma_bf16_16x8x16(sacc[ni], qhi[kk], bh0, bh1);
            }
        }

        // ---- causal mask ----
        if (jt >= 2 * qt) {
            const int jg0 = jt * 64;
            #pragma unroll
            for (int ni = 0; ni < 8; ni++) {
                const int jg = jg0 + ni * 8 + 2 * tq;
                if (jg     > ig0)      sacc[ni][0] = -1e30f;
                if (jg + 1 > ig0)      sacc[ni][1] = -1e30f;
                if (jg     > ig0 + 8)  sacc[ni][2] = -1e30f;
                if (jg + 1 > ig0 + 8)  sacc[ni][3] = -1e30f;
            }
        }

        // ---- online softmax ----
        float mloc0 = -1e30f, mloc1 = -1e30f;
        #pragma unroll
        for (int ni = 0; ni < 8; ni++) {
            mloc0 = fmaxf(mloc0, fmaxf(sacc[ni][0], sacc[ni][1]));
            mloc1 = fmaxf(mloc1, fmaxf(sacc[ni][2], sacc[ni][3]));
        }
        #pragma unroll
        for (int off = 1; off < 4; off <<= 1) {
            mloc0 = fmaxf(mloc0, __shfl_xor_sync(0xffffffffu, mloc0, off));
            mloc1 = fmaxf(mloc1, __shfl_xor_sync(0xffffffffu, mloc1, off));
        }
        const float mnew0 = fmaxf(m_i[0], mloc0);
        const float mnew1 = fmaxf(m_i[1], mloc1);
        const float al0 = __expf(m_i[0] - mnew0);
        const float al1 = __expf(m_i[1] - mnew1);
        float ps0 = 0.f, ps1 = 0.f;
        #pragma unroll
        for (int ni = 0; ni < 8; ni++) {
            sacc[ni][0] = __expf(sacc[ni][0] - mnew0);
            sacc[ni][1] = __expf(sacc[ni][1] - mnew0);
            sacc[ni][2] = __expf(sacc[ni][2] - mnew1);
            sacc[ni][3] = __expf(sacc[ni][3] - mnew1);
            ps0 += sacc[ni][0] + sacc[ni][1];
            ps1 += sacc[ni][2] + sacc[ni][3];
        }
        #pragma unroll
        for (int off = 1; off < 4; off <<= 1) {
            ps0 += __shfl_xor_sync(0xffffffffu, ps0, off);
            ps1 += __shfl_xor_sync(0xffffffffu, ps1, off);
        }
        l_i[0] = l_i[0] * al0 + ps0;  m_i[0] = mnew0;
        l_i[1] = l_i[1] * al1 + ps1;  m_i[1] = mnew1;
        #pragma unroll
        for (int ni = 0; ni < 8; ni++) {
            oacc[ni][0] *= al0; oacc[ni][1] *= al0;
            oacc[ni][2] *= al1; oacc[ni][3] *= al1;
        }

        // ---- split+store P to bf16 planes (warp-local rows) ----
        __nv_bfloat16* Phi = (__nv_bfloat16*)fsm;
        __nv_bfloat16* Plo = (__nv_bfloat16*)(fsm + QP_B);
        #pragma unroll
        for (int ni = 0; ni < 8; ni++) {
            const int col = ni * 8 + 2 * tq;
            uint32_t hp0, lp0, hp1, lp1;
            splitb(sacc[ni][0], sacc[ni][1], hp0, lp0);
            splitb(sacc[ni][2], sacc[ni][3], hp1, lp1);
            *(uint32_t*)&Phi[(r0 + quad)     * FPAD + col] = hp0;
            *(uint32_t*)&Plo[(r0 + quad)     * FPAD + col] = lp0;
            *(uint32_t*)&Phi[(r0 + quad + 8) * FPAD + col] = hp1;
            *(uint32_t*)&Plo[(r0 + quad + 8) * FPAD + col] = lp1;
        }
        __syncwarp();

        // ---- O += P V (3xBF16, all operands pre-split) ----
        #pragma unroll
        for (int kk = 0; kk < 4; kk++) {
            const int k0 = kk * 16 + 2 * tq;
            const int rw0 = (r0 + quad) * FPAD;
            uint32_t ph[4], pl[4];
            ph[0] = *(const uint32_t*)&Phi[rw0 + k0];
            ph[1] = *(const uint32_t*)&Phi[rw0 + 8*FPAD + k0];
            ph[2] = *(const uint32_t*)&Phi[rw0 + k0 + 8];
            ph[3] = *(const uint32_t*)&Phi[rw0 + 8*FPAD + k0 + 8];
            pl[0] = *(const uint32_t*)&Plo[rw0 + k0];
            pl[1] = *(const uint32_t*)&Plo[rw0 + 8*FPAD + k0];
            pl[2] = *(const uint32_t*)&Plo[rw0 + k0 + 8];
            pl[3] = *(const uint32_t*)&Plo[rw0 + 8*FPAD + k0 + 8];
            #pragma unroll
            for (int ni = 0; ni < 8; ni++) {
                const int rw = (ni * 8 + quad) * FPAD;
                uint32_t bh0 = *(const uint32_t*)&VThi[rw + k0];
                uint32_t bh1 = *(const uint32_t*)&VThi[rw + k0 + 8];
                uint32_t bl0 = *(const uint32_t*)&VTlo[rw + k0];
                uint32_t bl1 = *(const uint32_t*)&VTlo[rw + k0 + 8];
                mma_bf16_16x8x16(oacc[ni], pl, bh0, bh1);
                mma_bf16_16x8x16(oacc[ni], ph, bl0, bl1);
                mma_bf16_16x8x16(oacc[ni], ph, bh0, bh1);
            }
        }
        __syncwarp();
    }

    // ---- normalize + write bf16 hi/lo att to [B,S,H,HD] ----
    const int bidx = bh >> 4, h = bh & 15;
    #pragma unroll
    for (int half = 0; half < 2; half++) {
        const float inv = 1.0f / l_i[half];
        const int s = qt * 128 + r0 + quad + half * 8;
        const size_t dof = ((size_t)bidx * Seq + s) * Hn * Hd + (size_t)h * Hd;
        #pragma unroll
        for (int ni = 0; ni < 8; ni++) {
            float vx = oacc[ni][half * 2 + 0] * inv;
            float vy = oacc[ni][half * 2 + 1] * inv;
            uint32_t hp, lp;
            splitb(vx, vy, hp, lp);
            *(uint32_t*)&g_ahi[dof + ni * 8 + 2 * tq] = hp;
            *(uint32_t*)&g_alo[dof + ni * 8 + 2 * tq] = lp;
        }
    }
}

// ---------------------------------------------------------------------------
extern "C" void kernel_launch(void* const* d_in, const int* in_sizes, int n_in,
                              void* d_out, int out_size)
{
    (void)in_sizes; (void)n_in; (void)out_size;
    const float* X    = (const float*)d_in[0];
    const float* Wq   = (const float*)d_in[1];
    const float* bq   = (const float*)d_in[2];
    const float* Wk   = (const float*)d_in[3];
    const float* bk   = (const float*)d_in[4];
    const float* Wv   = (const float*)d_in[5];
    const float* bv   = (const float*)d_in[6];
    const float* Wo   = (const float*)d_in[7];
    const float* bo   = (const float*)d_in[8];
    const float* comp = (const float*)d_in[9];
    float* out = (float*)d_out;

    cudaFuncSetAttribute(qkv_mma,   cudaFuncAttributeMaxDynamicSharedMemorySize, GEMM_SMEM_BYTES);
    cudaFuncSetAttribute(proj_mma,  cudaFuncAttributeMaxDynamicSharedMemorySize, GEMM_SMEM_BYTES);
    cudaFuncSetAttribute(flash_mma, cudaFuncAttributeMaxDynamicSharedMemorySize, FLASH_SMEM_BYTES);

    dim3 gS(512, 5);                     // split X + 4 W's
    split_xw<<<gS, 256>>>(X, Wq, Wk, Wv, Wo);

    dim3 gQKV(Dm/128, Mrows/128, 3);     // (8, 64, 3)
    qkv_mma<<<gQKV, 256, GEMM_SMEM_BYTES>>>(bq, bk, bv);

    dim3 gFA(Seq/128, Bsz*Hn);           // (16, 64)
    flash_mma<<<gFA, 256, FLASH_SMEM_BYTES>>>();

    dim3 gP(Dm/128, Mrows/128);          // (8, 64)
    proj_mma<<<gP, 256, GEMM_SMEM_BYTES>>>(bo, comp, out);
}

// round 13
// speedup vs baseline: 2.4201x; 1.0088x over previous
#include <cuda_runtime.h>
#include <cuda_bf16.h>
#include <cstdint>

#define Bsz 4
#define Seq 2048
#define Dm  1024
#define Hn  16
#define Hd  64
#define Mrows (Bsz*Seq)   // 8192

// Scratch (allocation-free rule: __device__ globals)
__device__ __nv_bfloat16 g_xhi[Mrows*Dm],  g_xlo[Mrows*Dm];
__device__ __nv_bfloat16 g_whi[4][Dm*Dm],  g_wlo[4][Dm*Dm];
__device__ __nv_bfloat16 g_ahi[Bsz*Seq*Dm], g_alo[Bsz*Seq*Dm];
__device__ __nv_bfloat16 g_qhi[Bsz*Hn*Seq*Hd], g_qlo[Bsz*Hn*Seq*Hd];  // pre-scaled 1/8
__device__ __nv_bfloat16 g_khi[Bsz*Hn*Seq*Hd], g_klo[Bsz*Hn*Seq*Hd];
__device__ __nv_bfloat16 g_vthi[Bsz*Hn*Hd*Seq], g_vtlo[Bsz*Hn*Hd*Seq]; // [B,H,HD,S]

// ===========================================================================
// Common helpers
// ===========================================================================
__device__ __forceinline__ uint32_t smem_u32(const void* p) {
    uint32_t a;
    asm("{ .reg .u64 t; cvta.to.shared.u64 t, %1; cvt.u32.u64 %0, t; }"
        : "=r"(a) : "l"(p));
    return a;
}

#define CP16(dst, src) \
    asm volatile("cp.async.cg.shared.global [%0], [%1], 16;" :: "r"(dst), "l"(src))
#define CP_COMMIT()  asm volatile("cp.async.commit_group;" ::: "memory")
#define CP_WAIT1()   asm volatile("cp.async.wait_group 1;" ::: "memory")
#define CP_WAIT0()   asm volatile("cp.async.wait_group 0;" ::: "memory")

#define LDSM4(r, addr) \
    asm volatile("ldmatrix.sync.aligned.m8n8.x4.shared.b16 {%0,%1,%2,%3}, [%4];" \
        : "=r"((r)[0]), "=r"((r)[1]), "=r"((r)[2]), "=r"((r)[3]) : "r"(addr))

__device__ __forceinline__ void mma_bf16_16x8x16(float c[4], const uint32_t a[4],
                                                 uint32_t b0, uint32_t b1) {
    asm volatile(
        "mma.sync.aligned.m16n8k16.row.col.f32.bf16.bf16.f32 "
        "{%0,%1,%2,%3}, {%4,%5,%6,%7}, {%8,%9}, {%0,%1,%2,%3};"
        : "+f"(c[0]), "+f"(c[1]), "+f"(c[2]), "+f"(c[3])
        : "r"(a[0]), "r"(a[1]), "r"(a[2]), "r"(a[3]), "r"(b0), "r"(b1));
}

// Split pair of fp32 -> packed bf16x2 hi + lo
__device__ __forceinline__ void splitb(float x, float y, uint32_t& hi, uint32_t& lo) {
    __nv_bfloat162 h;
    h.x = __float2bfloat16_rn(x);
    h.y = __float2bfloat16_rn(y);
    __nv_bfloat162 l;
    l.x = __float2bfloat16_rn(x - __bfloat162float(h.x));
    l.y = __float2bfloat16_rn(y - __bfloat162float(h.y));
    hi = *(uint32_t*)&h;
    lo = *(uint32_t*)&l;
}

// ===========================================================================
// Split pre-pass: X and 4 W matrices -> bf16 hi/lo planes
// ===========================================================================
__global__ __launch_bounds__(256)
void split_xw(const float* __restrict__ X,
              const float* __restrict__ Wq, const float* __restrict__ Wk,
              const float* __restrict__ Wv, const float* __restrict__ Wo)
{
    const int z = blockIdx.y;
    const float* src;
    __nv_bfloat16 *dhi, *dlo;
    int n4;
    if (z == 0)      { src = X;  dhi = g_xhi;    dlo = g_xlo;    n4 = Mrows*Dm/4; }
    else if (z == 1) { src = Wq; dhi = g_whi[0]; dlo = g_wlo[0]; n4 = Dm*Dm/4; }
    else if (z == 2) { src = Wk; dhi = g_whi[1]; dlo = g_wlo[1]; n4 = Dm*Dm/4; }
    else if (z == 3) { src = Wv; dhi = g_whi[2]; dlo = g_wlo[2]; n4 = Dm*Dm/4; }
    else             { src = Wo; dhi = g_whi[3]; dlo = g_wlo[3]; n4 = Dm*Dm/4; }

    for (int i = blockIdx.x * blockDim.x + threadIdx.x; i < n4;
         i += gridDim.x * blockDim.x) {
        float4 v = ((const float4*)src)[i];
        uint32_t h0, l0, h1, l1;
        splitb(v.x, v.y, h0, l0);
        splitb(v.z, v.w, h1, l1);
        *(uint2*)&dhi[4*i] = make_uint2(h0, h1);
        *(uint2*)&dlo[4*i] = make_uint2(l0, l1);
    }
}

// ===========================================================================
// 3xBF16 GEMM on pre-split planes, LDSM fragment loads. C[128x128], K=1024.
// ===========================================================================
#define KTB   32
#define PADB  40
#define PLANE_B (128*PADB*2)          // 10240 bytes per plane
#define STG_B   (4*PLANE_B)
#define GEMM_SMEM_BYTES (2*STG_B)     // 81920

__device__ __forceinline__ void gemm_bf16_tile(const __nv_bfloat16* __restrict__ Ahi_g,
                                               const __nv_bfloat16* __restrict__ Alo_g,
                                               const __nv_bfloat16* __restrict__ Bhi_g,
                                               const __nv_bfloat16* __restrict__ Blo_g,
                                               int row0, int col0,
                                               float acc[4][4][4])
{
    extern __shared__ char smc[];
    const int tid  = threadIdx.x;
    const int wid  = tid >> 5, lane = tid & 31;
    const int warpM = wid >> 2, warpN = wid & 3;

    uint32_t dof[2];
    size_t offA[2], offB[2];
    const uint32_t smb = smem_u32(smc);
    #pragma unroll
    for (int it = 0; it < 2; it++) {
        int id = it * 256 + tid;
        int r  = id >> 2;
        int c  = id & 3;
        dof[it]  = smb + (uint32_t)(r * 80 + c * 16);
        offA[it] = (size_t)(row0 + r) * Dm + c * 8;
        offB[it] = (size_t)(col0 + r) * Dm + c * 8;
    }

    // LDSM lane bases
    const uint32_t aBase = smb +
        (uint32_t)((warpM * 64 + (lane & 15)) * 80 + ((lane >> 4) * 16));
    const uint32_t bBase = smb + 2*PLANE_B +
        (uint32_t)((warpN * 32 + (lane & 7) + ((lane >> 4) << 3)) * 80 +
                   (((lane >> 3) & 1) * 16));

    #pragma unroll
    for (int it = 0; it < 2; it++) {
        CP16(dof[it],               Ahi_g + offA[it]);
        CP16(dof[it] +   PLANE_B,   Alo_g + offA[it]);
        CP16(dof[it] + 2*PLANE_B,   Bhi_g + offB[it]);
        CP16(dof[it] + 3*PLANE_B,   Blo_g + offB[it]);
    }
    CP_COMMIT();

    const int NST = Dm / KTB;
    for (int s = 0; s < NST; s++) {
        const int cur = s & 1;
        if (s + 1 < NST) {
            const uint32_t bo = (uint32_t)((s + 1) & 1) * STG_B;
            const int ko = (s + 1) * KTB;
            #pragma unroll
            for (int it = 0; it < 2; it++) {
                CP16(dof[it] + bo,               Ahi_g + offA[it] + ko);
                CP16(dof[it] + bo +   PLANE_B,   Alo_g + offA[it] + ko);
                CP16(dof[it] + bo + 2*PLANE_B,   Bhi_g + offB[it] + ko);
                CP16(dof[it] + bo + 3*PLANE_B,   Blo_g + offB[it] + ko);
            }
            CP_COMMIT();
            CP_WAIT1();
        } else {
            CP_WAIT0();
        }
        __syncthreads();

        const uint32_t sb = (uint32_t)cur * STG_B;

        #pragma unroll
        for (int kk = 0; kk < 2; kk++) {
            uint32_t ah[4][4], al[4][4], bh[2][4], bl[2][4];
            #pragma unroll
            for (int mi = 0; mi < 4; mi++) {
                LDSM4(ah[mi], aBase + sb + mi*(16*80) + kk*32);
                LDSM4(al[mi], aBase + sb + PLANE_B + mi*(16*80) + kk*32);
            }
            #pragma unroll
            for (int p = 0; p < 2; p++) {
                LDSM4(bh[p], bBase + sb + p*(16*80) + kk*32);
                LDSM4(bl[p], bBase + sb + PLANE_B + p*(16*80) + kk*32);
            }
            #pragma unroll
            for (int mi = 0; mi < 4; mi++)
                #pragma unroll
                for (int ni = 0; ni < 4; ni++) {
                    const uint32_t b0h = bh[ni>>1][(ni&1)*2],
                                   b1h = bh[ni>>1][(ni&1)*2+1];
                    const uint32_t b0l = bl[ni>>1][(ni&1)*2],
                                   b1l = bl[ni>>1][(ni&1)*2+1];
                    mma_bf16_16x8x16(acc[mi][ni], al[mi], b0h, b1h);
                    mma_bf16_16x8x16(acc[mi][ni], ah[mi], b0l, b1l);
                    mma_bf16_16x8x16(acc[mi][ni], ah[mi], b0h, b1h);
                }
        }
        __syncthreads();
    }
}

// ===========================================================================
// QKV projection; epilogue writes bf16 hi/lo planes.
// Q pre-scaled 1/8; V written TRANSPOSED [B,H,HD,S].
// ===========================================================================
__global__ __launch_bounds__(256)
void qkv_mma(const float* __restrict__ bq, const float* __restrict__ bk,
             const float* __restrict__ bv)
{
    const int z = blockIdx.z;
    const float* bias = (z == 0) ? bq : (z == 1) ? bk : bv;
    const float scale = (z == 0) ? 0.125f : 1.0f;

    float acc[4][4][4];
    #pragma unroll
    for (int mi = 0; mi < 4; mi++)
        #pragma unroll
        for (int ni = 0; ni < 4; ni++)
            #pragma unroll
            for (int j = 0; j < 4; j++) acc[mi][ni][j] = 0.f;

    const int row0 = blockIdx.y * 128;
    const int col0 = blockIdx.x * 128;
    gemm_bf16_tile(g_xhi, g_xlo, g_whi[z], g_wlo[z], row0, col0, acc);

    const int tid  = threadIdx.x;
    const int wid  = tid >> 5, lane = tid & 31;
    const int warpM = wid >> 2, warpN = wid & 3;
    const int quad = lane >> 2, tq = lane & 3;

    #pragma unroll
    for (int mi = 0; mi < 4; mi++) {
        #pragma unroll
        for (int half = 0; half < 2; half++) {
            const int r = row0 + warpM * 64 + mi * 16 + quad + half * 8;
            const int b = r >> 11;
            const int sq = r & 2047;
            #pragma unroll
            for (int ni = 0; ni < 4; ni++) {
                const int c  = col0 + warpN * 32 + ni * 8 + 2 * tq;
                const int h  = c >> 6;
                const int hd = c & 63;
                float2 bb = *(const float2*)&bias[c];
                float vx = (acc[mi][ni][half*2+0] + bb.x) * scale;
                float vy = (acc[mi][ni][half*2+1] + bb.y) * scale;
                uint32_t hp, lp;
                splitb(vx, vy, hp, lp);
                if (z == 2) {
                    const size_t ot = ((size_t)(b * Hn + h) * Hd + hd) * Seq + sq;
                    __nv_bfloat162 h2 = *(__nv_bfloat162*)&hp;
                    __nv_bfloat162 l2 = *(__nv_bfloat162*)&lp;
                    g_vthi[ot]       = h2.x;  g_vthi[ot + Seq] = h2.y;
                    g_vtlo[ot]       = l2.x;  g_vtlo[ot + Seq] = l2.y;
                } else {
                    const size_t o = (((size_t)(b * Hn + h) * Seq + sq) * Hd + hd);
                    if (z == 0) {
                        *(uint32_t*)&g_qhi[o] = hp;
                        *(uint32_t*)&g_qlo[o] = lp;
                    } else {
                        *(uint32_t*)&g_khi[o] = hp;
                        *(uint32_t*)&g_klo[o] = lp;
                    }
                }
            }
        }
    }
}

// ===========================================================================
// Output projection: out = att @ Wo^T + bo + comp
// ===========================================================================
__global__ __launch_bounds__(256)
void proj_mma(const float* __restrict__ bo, const float* __restrict__ comp,
              float* __restrict__ out)
{
    float acc[4][4][4];
    #pragma unroll
    for (int mi = 0; mi < 4; mi++)
        #pragma unroll
        for (int ni = 0; ni < 4; ni++)
            #pragma unroll
            for (int j = 0; j < 4; j++) acc[mi][ni][j] = 0.f;

    const int row0 = blockIdx.y * 128;
    const int col0 = blockIdx.x * 128;
    gemm_bf16_tile(g_ahi, g_alo, g_whi[3], g_wlo[3], row0, col0, acc);

    const int tid  = threadIdx.x;
    const int wid  = tid >> 5, lane = tid & 31;
    const int warpM = wid >> 2, warpN = wid & 3;
    const int quad = lane >> 2, tq = lane & 3;

    #pragma unroll
    for (int mi = 0; mi < 4; mi++) {
        #pragma unroll
        for (int half = 0; half < 2; half++) {
            const int r = row0 + warpM * 64 + mi * 16 + quad + half * 8;
            #pragma unroll
            for (int ni = 0; ni < 4; ni++) {
                const int c = col0 + warpN * 32 + ni * 8 + 2 * tq;
                float2 bb = *(const float2*)&bo[c];
                float2 cc = *(const float2*)&comp[c];
                float2 v;
                v.x = acc[mi][ni][half * 2 + 0] + bb.x + cc.x;
                v.y = acc[mi][ni][half * 2 + 1] + bb.y + cc.y;
                *(float2*)(out + (size_t)r * Dm + c) = v;
            }
        }
    }
}

// ===========================================================================
// Flash attention, 3xBF16 + LDSM. BM=128, BN=64, 256 threads (8 warps).
// P packed directly from S C-fragments (no smem round-trip).
// ===========================================================================
#define FPAD 72
#define FROW 144
#define QP_B   (128*FROW)           // 18432: Q staging only
#define KPLANE (64*FROW)            // 9216
#define FSTGB  (4*KPLANE)           // 36864: Khi|Klo|VThi|VTlo
#define FLASH_SMEM_BYTES (QP_B + 2*FSTGB)   // 92160

__global__ __launch_bounds__(256)
void flash_mma()
{
    const int qt = blockIdx.x;           // 0..15
    const int bh = blockIdx.y;           // 0..63
    const size_t bho = (size_t)bh * Seq * Hd;    // K/Q base
    const size_t bhv = (size_t)bh * Hd * Seq;    // VT base

    extern __shared__ char fsm[];
    const uint32_t qpb = smem_u32(fsm);          // Q staging
    const uint32_t st0 = qpb + QP_B;             // KV stage 0

    const int tid  = threadIdx.x;
    const int wid  = tid >> 5, lane = tid & 31;
    const int quad = lane >> 2, tq = lane & 3;
    const int r0   = wid * 16;

    // cp.async slots: 512 chunks per plane, 2/thread
    uint32_t koff[2];
    size_t ksrc[2], vsrc[2];
    #pragma unroll
    for (int i = 0; i < 2; i++) {
        int id = i * 256 + tid;
        int row = id >> 3, c = id & 7;
        koff[i] = (uint32_t)(row * FROW + c * 16);
        ksrc[i] = (size_t)row * Hd + c * 8;
        vsrc[i] = (size_t)row * Seq + c * 8;
    }

    // LDSM lane bases
    const uint32_t qBase = qpb +
        (uint32_t)((r0 + (lane & 15)) * FROW + (lane >> 4) * 16);
    const uint32_t kBase = st0 +
        (uint32_t)(((lane & 7) + ((lane >> 4) << 3)) * FROW +
                   (((lane >> 3) & 1) * 16));

    // ---- Prologue: Qhi + stage 0, then Qlo ----
    #pragma unroll
    for (int i = 0; i < 4; i++) {
        int id = i * 256 + tid;
        int row = id >> 3, c = id & 7;
        CP16(qpb + (uint32_t)(row * FROW + c * 16),
             g_qhi + bho + (size_t)(qt * 128 + row) * Hd + c * 8);
    }
    #pragma unroll
    for (int i = 0; i < 2; i++) {
        CP16(st0 + koff[i],              g_khi  + bho + ksrc[i]);
        CP16(st0 + KPLANE + koff[i],     g_klo  + bho + ksrc[i]);
        CP16(st0 + 2*KPLANE + koff[i],   g_vthi + bhv + vsrc[i]);
        CP16(st0 + 3*KPLANE + koff[i],   g_vtlo + bhv + vsrc[i]);
    }
    CP_COMMIT();
    CP_WAIT0();
    __syncthreads();

    uint32_t qhi[4][4], qlo[4][4];
    #pragma unroll
    for (int kk = 0; kk < 4; kk++) LDSM4(qhi[kk], qBase + kk * 32);
    __syncthreads();
    #pragma unroll
    for (int i = 0; i < 4; i++) {
        int id = i * 256 + tid;
        int row = id >> 3, c = id & 7;
        CP16(qpb + (uint32_t)(row * FROW + c * 16),
             g_qlo + bho + (size_t)(qt * 128 + row) * Hd + c * 8);
    }
    CP_COMMIT();
    CP_WAIT0();
    __syncthreads();
    #pragma unroll
    for (int kk = 0; kk < 4; kk++) LDSM4(qlo[kk], qBase + kk * 32);

    float m_i[2] = { -1e30f, -1e30f };
    float l_i[2] = { 0.f, 0.f };
    float oacc[8][4];
    #pragma unroll
    for (int ni = 0; ni < 8; ni++)
        #pragma unroll
        for (int j = 0; j < 4; j++) oacc[ni][j] = 0.f;

    const int jend = 2 * qt + 1;
    const int ig0  = qt * 128 + r0 + quad;

    for (int jt = 0; jt <= jend; jt++) {
        __syncthreads();

        const int cur = jt & 1;
        if (jt + 1 <= jend) {
            const uint32_t sb = st0 + (uint32_t)((jt + 1) & 1) * FSTGB;
            const size_t kro = (size_t)((jt + 1) * 64) * Hd;
            const size_t vro = (size_t)((jt + 1) * 64);
            #pragma unroll
            for (int i = 0; i < 2; i++) {
                CP16(sb + koff[i],              g_khi  + bho + kro + ksrc[i]);
                CP16(sb + KPLANE + koff[i],     g_klo  + bho + kro + ksrc[i]);
                CP16(sb + 2*KPLANE + koff[i],   g_vthi + bhv + vro + vsrc[i]);
                CP16(sb + 3*KPLANE + koff[i],   g_vtlo + bhv + vro + vsrc[i]);
            }
            CP_COMMIT();
            CP_WAIT1();
        } else {
            CP_WAIT0();
        }
        __syncthreads();

        // Causal skip: at the last KV tile, rows 0-63 (warps 0-3) are fully
        // masked -> contribute exactly zero; skip their compute entirely.
        if (jt == jend && wid < 4) continue;

        const uint32_t kB = kBase + (uint32_t)cur * FSTGB;
        const uint32_t vB = kB + 2 * KPLANE;

        // ---- S = Q K^T (3xBF16, LDSM B-frags) ----
        float sacc[8][4];
        #pragma unroll
        for (int ni = 0; ni < 8; ni++)
            #pragma unroll
            for (int j = 0; j < 4; j++) sacc[ni][j] = 0.f;

        #pragma unroll
        for (int p = 0; p < 4; p++) {
            #pragma unroll
            for (int kk = 0; kk < 4; kk++) {
                uint32_t kh[4], kl[4];
                LDSM4(kh, kB + p * (16 * FROW) + kk * 32);
                LDSM4(kl, kB + KPLANE + p * (16 * FROW) + kk * 32);
                mma_bf16_16x8x16(sacc[2*p],   qlo[kk], kh[0], kh[1]);
                mma_bf16_16x8x16(sacc[2*p],   qhi[kk], kl[0], kl[1]);
                mma_bf16_16x8x16(sacc[2*p],   qhi[kk], kh[0], kh[1]);
                mma_bf16_16x8x16(sacc[2*p+1], qlo[kk], kh[2], kh[3]);
                mma_bf16_16x8x16(sacc[2*p+1], qhi[kk], kl[2], kl[3]);
                mma_bf16_16x8x16(sacc[2*p+1], qhi[kk], kh[2], kh[3]);
            }
        }

        // ---- causal mask ----
        if (jt >= 2 * qt) {
            const int jg0 = jt * 64;
            #pragma unroll
            for (int ni = 0; ni < 8; ni++) {
                const int jg = jg0 + ni * 8 + 2 * tq;
                if (jg     > ig0)      sacc[ni][0] = -1e30f;
                if (jg + 1 > ig0)      sacc[ni][1] = -1e30f;
                if (jg     > ig0 + 8)  sacc[ni][2] = -1e30f;
                if (jg + 1 > ig0 + 8)  sacc[ni][3] = -1e30f;
            }
        }

        // ---- online softmax ----
        float mloc0 = -1e30f, mloc1 = -1e30f;
        #pragma unroll
        for (int ni = 0; ni < 8; ni++) {
            mloc0 = fmaxf(mloc0, fmaxf(sacc[ni][0], sacc[ni][1]));
            mloc1 = fmaxf(mloc1, fmaxf(sacc[ni][2], sacc[ni][3]));
        }
        #pragma unroll
        for (int off = 1; off < 4; off <<= 1) {
            mloc0 = fmaxf(mloc0, __shfl_xor_sync(0xffffffffu, mloc0, off));
            mloc1 = fmaxf(mloc1, __shfl_xor_sync(0xffffffffu, mloc1, off));
        }
        const float mnew0 = fmaxf(m_i[0], mloc0);
        const float mnew1 = fmaxf(m_i[1], mloc1);
        const float al0 = __expf(m_i[0] - mnew0);
        const float al1 = __expf(m_i[1] - mnew1);
        float ps0 = 0.f, ps1 = 0.f;
        #pragma unroll
        for (int ni = 0; ni < 8; ni++) {
            sacc[ni][0] = __expf(sacc[ni][0] - mnew0);
            sacc[ni][1] = __expf(sacc[ni][1] - mnew0);
            sacc[ni][2] = __expf(sacc[ni][2] - mnew1);
            sacc[ni][3] = __expf(sacc[ni][3] - mnew1);
            ps0 += sacc[ni][0] + sacc[ni][1];
            ps1 += sacc[ni][2] + sacc[ni][3];
        }
        #pragma unroll
        for (int off = 1; off < 4; off <<= 1) {
            ps0 += __shfl_xor_sync(0xffffffffu, ps0, off);
            ps1 += __shfl_xor_sync(0xffffffffu, ps1, off);
        }
        l_i[0] = l_i[0] * al0 + ps0;  m_i[0] = mnew0;
        l_i[1] = l_i[1] * al1 + ps1;  m_i[1] = mnew1;
        #pragma unroll
        for (int ni = 0; ni < 8; ni++) {
            oacc[ni][0] *= al0; oacc[ni][1] *= al0;
            oacc[ni][2] *= al1; oacc[ni][3] *= al1;
        }

        // ---- O += P V: P packed DIRECTLY from S C-fragments ----
        #pragma unroll
        for (int kk = 0; kk < 4; kk++) {
            uint32_t ph[4], pl[4];
            splitb(sacc[2*kk][0],   sacc[2*kk][1],   ph[0], pl[0]);
            splitb(sacc[2*kk][2],   sacc[2*kk][3],   ph[1], pl[1]);
            splitb(sacc[2*kk+1][0], sacc[2*kk+1][1], ph[2], pl[2]);
            splitb(sacc[2*kk+1][2], sacc[2*kk+1][3], ph[3], pl[3]);
            #pragma unroll
            for (int p = 0; p < 4; p++) {
                uint32_t vh[4], vl[4];
                LDSM4(vh, vB + p * (16 * FROW) + kk * 32);
                LDSM4(vl, vB + KPLANE + p * (16 * FROW) + kk * 32);
                mma_bf16_16x8x16(oacc[2*p],   pl, vh[0], vh[1]);
                mma_bf16_16x8x16(oacc[2*p],   ph, vl[0], vl[1]);
                mma_bf16_16x8x16(oacc[2*p],   ph, vh[0], vh[1]);
                mma_bf16_16x8x16(oacc[2*p+1], pl, vh[2], vh[3]);
                mma_bf16_16x8x16(oacc[2*p+1], ph, vl[2], vl[3]);
                mma_bf16_16x8x16(oacc[2*p+1], ph, vh[2], vh[3]);
            }
        }
    }

    // ---- normalize + write bf16 hi/lo att to [B,S,H,HD] ----
    const int bidx = bh >> 4, h = bh & 15;
    #pragma unroll
    for (int half = 0; half < 2; half++) {
        const float inv = 1.0f / l_i[half];
        const int s = qt * 128 + r0 + quad + half * 8;
        const size_t dof = ((size_t)bidx * Seq + s) * Hn * Hd + (size_t)h * Hd;
        #pragma unroll
        for (int ni = 0; ni < 8; ni++) {
            float vx = oacc[ni][half * 2 + 0] * inv;
            float vy = oacc[ni][half * 2 + 1] * inv;
            uint32_t hp, lp;
            splitb(vx, vy, hp, lp);
            *(uint32_t*)&g_ahi[dof + ni * 8 + 2 * tq] = hp;
            *(uint32_t*)&g_alo[dof + ni * 8 + 2 * tq] = lp;
        }
    }
}

// ---------------------------------------------------------------------------
extern "C" void kernel_launch(void* const* d_in, const int* in_sizes, int n_in,
                              void* d_out, int out_size)
{
    (void)in_sizes; (void)n_in; (void)out_size;
    const float* X    = (const float*)d_in[0];
    const float* Wq   = (const float*)d_in[1];
    const float* bq   = (const float*)d_in[2];
    const float* Wk   = (const float*)d_in[3];
    const float* bk   = (const float*)d_in[4];
    const float* Wv   = (const float*)d_in[5];
    const float* bv   = (const float*)d_in[6];
    const float* Wo   = (const float*)d_in[7];
    const float* bo   = (const float*)d_in[8];
    const float* comp = (const float*)d_in[9];
    float* out = (float*)d_out;

    cudaFuncSetAttribute(qkv_mma,   cudaFuncAttributeMaxDynamicSharedMemorySize, GEMM_SMEM_BYTES);
    cudaFuncSetAttribute(proj_mma,  cudaFuncAttributeMaxDynamicSharedMemorySize, GEMM_SMEM_BYTES);
    cudaFuncSetAttribute(flash_mma, cudaFuncAttributeMaxDynamicSharedMemorySize, FLASH_SMEM_BYTES);

    dim3 gS(512, 5);                     // split X + 4 W's
    split_xw<<<gS, 256>>>(X, Wq, Wk, Wv, Wo);

    dim3 gQKV(Dm/128, Mrows/128, 3);     // (8, 64, 3)
    qkv_mma<<<gQKV, 256, GEMM_SMEM_BYTES>>>(bq, bk, bv);

    dim3 gFA(Seq/128, Bsz*Hn);           // (16, 64)
    flash_mma<<<gFA, 256, FLASH_SMEM_BYTES>>>();

    dim3 gP(Dm/128, Mrows/128);          // (8, 64)
    proj_mma<<<gP, 256, GEMM_SMEM_BYTES>>>(bo, comp, out);
}

// round 14
// speedup vs baseline: 2.6925x; 1.1126x over previous
#include <cuda_runtime.h>
#include <cuda_bf16.h>
#include <cstdint>

#define Bsz 4
#define Seq 2048
#define Dm  1024
#define Hn  16
#define Hd  64
#define Mrows (Bsz*Seq)   // 8192

// Scratch (allocation-free rule: __device__ globals)
__device__ __nv_bfloat16 g_xhi[Mrows*Dm],  g_xlo[Mrows*Dm];
__device__ __nv_bfloat16 g_whi[4][Dm*Dm],  g_wlo[4][Dm*Dm];
__device__ __nv_bfloat16 g_ahi[Bsz*Seq*Dm], g_alo[Bsz*Seq*Dm];
__device__ __nv_bfloat16 g_qhi[Bsz*Hn*Seq*Hd], g_qlo[Bsz*Hn*Seq*Hd];  // pre-scaled 1/8
__device__ __nv_bfloat16 g_khi[Bsz*Hn*Seq*Hd], g_klo[Bsz*Hn*Seq*Hd];
__device__ __nv_bfloat16 g_vthi[Bsz*Hn*Hd*Seq], g_vtlo[Bsz*Hn*Hd*Seq]; // [B,H,HD,S]

// ===========================================================================
// Common helpers
// ===========================================================================
__device__ __forceinline__ uint32_t smem_u32(const void* p) {
    uint32_t a;
    asm("{ .reg .u64 t; cvta.to.shared.u64 t, %1; cvt.u32.u64 %0, t; }"
        : "=r"(a) : "l"(p));
    return a;
}

#define CP16(dst, src) \
    asm volatile("cp.async.cg.shared.global [%0], [%1], 16;" :: "r"(dst), "l"(src))
#define CP_COMMIT()  asm volatile("cp.async.commit_group;" ::: "memory")
#define CP_WAIT1()   asm volatile("cp.async.wait_group 1;" ::: "memory")
#define CP_WAIT0()   asm volatile("cp.async.wait_group 0;" ::: "memory")

#define LDSM4(r, addr) \
    asm volatile("ldmatrix.sync.aligned.m8n8.x4.shared.b16 {%0,%1,%2,%3}, [%4];" \
        : "=r"((r)[0]), "=r"((r)[1]), "=r"((r)[2]), "=r"((r)[3]) : "r"(addr))

__device__ __forceinline__ void mma_bf16_16x8x16(float c[4], const uint32_t a[4],
                                                 uint32_t b0, uint32_t b1) {
    asm volatile(
        "mma.sync.aligned.m16n8k16.row.col.f32.bf16.bf16.f32 "
        "{%0,%1,%2,%3}, {%4,%5,%6,%7}, {%8,%9}, {%0,%1,%2,%3};"
        : "+f"(c[0]), "+f"(c[1]), "+f"(c[2]), "+f"(c[3])
        : "r"(a[0]), "r"(a[1]), "r"(a[2]), "r"(a[3]), "r"(b0), "r"(b1));
}

// Split pair of fp32 -> packed bf16x2 hi + lo
__device__ __forceinline__ void splitb(float x, float y, uint32_t& hi, uint32_t& lo) {
    __nv_bfloat162 h;
    h.x = __float2bfloat16_rn(x);
    h.y = __float2bfloat16_rn(y);
    __nv_bfloat162 l;
    l.x = __float2bfloat16_rn(x - __bfloat162float(h.x));
    l.y = __float2bfloat16_rn(y - __bfloat162float(h.y));
    hi = *(uint32_t*)&h;
    lo = *(uint32_t*)&l;
}

// ===========================================================================
// Split pre-pass: X and 4 W matrices -> bf16 hi/lo planes
// ===========================================================================
__global__ __launch_bounds__(256)
void split_xw(const float* __restrict__ X,
              const float* __restrict__ Wq, const float* __restrict__ Wk,
              const float* __restrict__ Wv, const float* __restrict__ Wo)
{
    const int z = blockIdx.y;
    const float* src;
    __nv_bfloat16 *dhi, *dlo;
    int n4;
    if (z == 0)      { src = X;  dhi = g_xhi;    dlo = g_xlo;    n4 = Mrows*Dm/4; }
    else if (z == 1) { src = Wq; dhi = g_whi[0]; dlo = g_wlo[0]; n4 = Dm*Dm/4; }
    else if (z == 2) { src = Wk; dhi = g_whi[1]; dlo = g_wlo[1]; n4 = Dm*Dm/4; }
    else if (z == 3) { src = Wv; dhi = g_whi[2]; dlo = g_wlo[2]; n4 = Dm*Dm/4; }
    else             { src = Wo; dhi = g_whi[3]; dlo = g_wlo[3]; n4 = Dm*Dm/4; }

    for (int i = blockIdx.x * blockDim.x + threadIdx.x; i < n4;
         i += gridDim.x * blockDim.x) {
        float4 v = ((const float4*)src)[i];
        uint32_t h0, l0, h1, l1;
        splitb(v.x, v.y, h0, l0);
        splitb(v.z, v.w, h1, l1);
        *(uint2*)&dhi[4*i] = make_uint2(h0, h1);
        *(uint2*)&dlo[4*i] = make_uint2(l0, l1);
    }
}

// ===========================================================================
// 3xBF16 GEMM on pre-split planes, LDSM fragment loads. C[128x128], K=1024.
// ===========================================================================
#define KTB   32
#define PADB  40
#define PLANE_B (128*PADB*2)          // 10240 bytes per plane
#define STG_B   (4*PLANE_B)
#define GEMM_SMEM_BYTES (2*STG_B)     // 81920

__device__ __forceinline__ void gemm_bf16_tile(const __nv_bfloat16* __restrict__ Ahi_g,
                                               const __nv_bfloat16* __restrict__ Alo_g,
                                               const __nv_bfloat16* __restrict__ Bhi_g,
                                               const __nv_bfloat16* __restrict__ Blo_g,
                                               int row0, int col0,
                                               float acc[4][4][4])
{
    extern __shared__ char smc[];
    const int tid  = threadIdx.x;
    const int wid  = tid >> 5, lane = tid & 31;
    const int warpM = wid >> 2, warpN = wid & 3;

    uint32_t dof[2];
    size_t offA[2], offB[2];
    const uint32_t smb = smem_u32(smc);
    #pragma unroll
    for (int it = 0; it < 2; it++) {
        int id = it * 256 + tid;
        int r  = id >> 2;
        int c  = id & 3;
        dof[it]  = smb + (uint32_t)(r * 80 + c * 16);
        offA[it] = (size_t)(row0 + r) * Dm + c * 8;
        offB[it] = (size_t)(col0 + r) * Dm + c * 8;
    }

    // LDSM lane bases
    const uint32_t aBase = smb +
        (uint32_t)((warpM * 64 + (lane & 15)) * 80 + ((lane >> 4) * 16));
    const uint32_t bBase = smb + 2*PLANE_B +
        (uint32_t)((warpN * 32 + (lane & 7) + ((lane >> 4) << 3)) * 80 +
                   (((lane >> 3) & 1) * 16));

    #pragma unroll
    for (int it = 0; it < 2; it++) {
        CP16(dof[it],               Ahi_g + offA[it]);
        CP16(dof[it] +   PLANE_B,   Alo_g + offA[it]);
        CP16(dof[it] + 2*PLANE_B,   Bhi_g + offB[it]);
        CP16(dof[it] + 3*PLANE_B,   Blo_g + offB[it]);
    }
    CP_COMMIT();

    const int NST = Dm / KTB;
    for (int s = 0; s < NST; s++) {
        const int cur = s & 1;
        if (s + 1 < NST) {
            const uint32_t bo = (uint32_t)((s + 1) & 1) * STG_B;
            const int ko = (s + 1) * KTB;
            #pragma unroll
            for (int it = 0; it < 2; it++) {
                CP16(dof[it] + bo,               Ahi_g + offA[it] + ko);
                CP16(dof[it] + bo +   PLANE_B,   Alo_g + offA[it] + ko);
                CP16(dof[it] + bo + 2*PLANE_B,   Bhi_g + offB[it] + ko);
                CP16(dof[it] + bo + 3*PLANE_B,   Blo_g + offB[it] + ko);
            }
            CP_COMMIT();
            CP_WAIT1();
        } else {
            CP_WAIT0();
        }
        __syncthreads();

        const uint32_t sb = (uint32_t)cur * STG_B;

        #pragma unroll
        for (int kk = 0; kk < 2; kk++) {
            uint32_t ah[4][4], al[4][4], bh[2][4], bl[2][4];
            #pragma unroll
            for (int mi = 0; mi < 4; mi++) {
                LDSM4(ah[mi], aBase + sb + mi*(16*80) + kk*32);
                LDSM4(al[mi], aBase + sb + PLANE_B + mi*(16*80) + kk*32);
            }
            #pragma unroll
            for (int p = 0; p < 2; p++) {
                LDSM4(bh[p], bBase + sb + p*(16*80) + kk*32);
                LDSM4(bl[p], bBase + sb + PLANE_B + p*(16*80) + kk*32);
            }
            #pragma unroll
            for (int mi = 0; mi < 4; mi++)
                #pragma unroll
                for (int ni = 0; ni < 4; ni++) {
                    const uint32_t b0h = bh[ni>>1][(ni&1)*2],
                                   b1h = bh[ni>>1][(ni&1)*2+1];
                    const uint32_t b0l = bl[ni>>1][(ni&1)*2],
                                   b1l = bl[ni>>1][(ni&1)*2+1];
                    mma_bf16_16x8x16(acc[mi][ni], al[mi], b0h, b1h);
                    mma_bf16_16x8x16(acc[mi][ni], ah[mi], b0l, b1l);
                    mma_bf16_16x8x16(acc[mi][ni], ah[mi], b0h, b1h);
                }
        }
        __syncthreads();
    }
}

// ===========================================================================
// QKV projection; epilogue writes bf16 hi/lo planes.
// Q pre-scaled 1/8; V written TRANSPOSED [B,H,HD,S].
// ===========================================================================
__global__ __launch_bounds__(256, 2)
void qkv_mma(const float* __restrict__ bq, const float* __restrict__ bk,
             const float* __restrict__ bv)
{
    const int z = blockIdx.z;
    const float* bias = (z == 0) ? bq : (z == 1) ? bk : bv;
    const float scale = (z == 0) ? 0.125f : 1.0f;

    float acc[4][4][4];
    #pragma unroll
    for (int mi = 0; mi < 4; mi++)
        #pragma unroll
        for (int ni = 0; ni < 4; ni++)
            #pragma unroll
            for (int j = 0; j < 4; j++) acc[mi][ni][j] = 0.f;

    const int row0 = blockIdx.y * 128;
    const int col0 = blockIdx.x * 128;
    gemm_bf16_tile(g_xhi, g_xlo, g_whi[z], g_wlo[z], row0, col0, acc);

    const int tid  = threadIdx.x;
    const int wid  = tid >> 5, lane = tid & 31;
    const int warpM = wid >> 2, warpN = wid & 3;
    const int quad = lane >> 2, tq = lane & 3;

    #pragma unroll
    for (int mi = 0; mi < 4; mi++) {
        #pragma unroll
        for (int half = 0; half < 2; half++) {
            const int r = row0 + warpM * 64 + mi * 16 + quad + half * 8;
            const int b = r >> 11;
            const int sq = r & 2047;
            #pragma unroll
            for (int ni = 0; ni < 4; ni++) {
                const int c  = col0 + warpN * 32 + ni * 8 + 2 * tq;
                const int h  = c >> 6;
                const int hd = c & 63;
                float2 bb = *(const float2*)&bias[c];
                float vx = (acc[mi][ni][half*2+0] + bb.x) * scale;
                float vy = (acc[mi][ni][half*2+1] + bb.y) * scale;
                uint32_t hp, lp;
                splitb(vx, vy, hp, lp);
                if (z == 2) {
                    const size_t ot = ((size_t)(b * Hn + h) * Hd + hd) * Seq + sq;
                    __nv_bfloat162 h2 = *(__nv_bfloat162*)&hp;
                    __nv_bfloat162 l2 = *(__nv_bfloat162*)&lp;
                    g_vthi[ot]       = h2.x;  g_vthi[ot + Seq] = h2.y;
                    g_vtlo[ot]       = l2.x;  g_vtlo[ot + Seq] = l2.y;
                } else {
                    const size_t o = (((size_t)(b * Hn + h) * Seq + sq) * Hd + hd);
                    if (z == 0) {
                        *(uint32_t*)&g_qhi[o] = hp;
                        *(uint32_t*)&g_qlo[o] = lp;
                    } else {
                        *(uint32_t*)&g_khi[o] = hp;
                        *(uint32_t*)&g_klo[o] = lp;
                    }
                }
            }
        }
    }
}

// ===========================================================================
// Output projection: out = att @ Wo^T + bo + comp
// ===========================================================================
__global__ __launch_bounds__(256, 2)
void proj_mma(const float* __restrict__ bo, const float* __restrict__ comp,
              float* __restrict__ out)
{
    float acc[4][4][4];
    #pragma unroll
    for (int mi = 0; mi < 4; mi++)
        #pragma unroll
        for (int ni = 0; ni < 4; ni++)
            #pragma unroll
            for (int j = 0; j < 4; j++) acc[mi][ni][j] = 0.f;

    const int row0 = blockIdx.y * 128;
    const int col0 = blockIdx.x * 128;
    gemm_bf16_tile(g_ahi, g_alo, g_whi[3], g_wlo[3], row0, col0, acc);

    const int tid  = threadIdx.x;
    const int wid  = tid >> 5, lane = tid & 31;
    const int warpM = wid >> 2, warpN = wid & 3;
    const int quad = lane >> 2, tq = lane & 3;

    #pragma unroll
    for (int mi = 0; mi < 4; mi++) {
        #pragma unroll
        for (int half = 0; half < 2; half++) {
            const int r = row0 + warpM * 64 + mi * 16 + quad + half * 8;
            #pragma unroll
            for (int ni = 0; ni < 4; ni++) {
                const int c = col0 + warpN * 32 + ni * 8 + 2 * tq;
                float2 bb = *(const float2*)&bo[c];
                float2 cc = *(const float2*)&comp[c];
                float2 v;
                v.x = acc[mi][ni][half * 2 + 0] + bb.x + cc.x;
                v.y = acc[mi][ni][half * 2 + 1] + bb.y + cc.y;
                *(float2*)(out + (size_t)r * Dm + c) = v;
            }
        }
    }
}

// ===========================================================================
// Flash attention, 3xBF16 + LDSM. BM=128, BN=64, 256 threads (8 warps).
// P packed directly from S C-fragments (no smem round-trip).
// ===========================================================================
#define FPAD 72
#define FROW 144
#define QP_B   (128*FROW)           // 18432: Q staging only
#define KPLANE (64*FROW)            // 9216
#define FSTGB  (4*KPLANE)           // 36864: Khi|Klo|VThi|VTlo
#define FLASH_SMEM_BYTES (QP_B + 2*FSTGB)   // 92160

__global__ __launch_bounds__(256, 2)
void flash_mma()
{
    const int qt = blockIdx.x;           // 0..15
    const int bh = blockIdx.y;           // 0..63
    const size_t bho = (size_t)bh * Seq * Hd;    // K/Q base
    const size_t bhv = (size_t)bh * Hd * Seq;    // VT base

    extern __shared__ char fsm[];
    const uint32_t qpb = smem_u32(fsm);          // Q staging
    const uint32_t st0 = qpb + QP_B;             // KV stage 0

    const int tid  = threadIdx.x;
    const int wid  = tid >> 5, lane = tid & 31;
    const int quad = lane >> 2, tq = lane & 3;
    const int r0   = wid * 16;

    // cp.async slots: 512 chunks per plane, 2/thread
    uint32_t koff[2];
    size_t ksrc[2], vsrc[2];
    #pragma unroll
    for (int i = 0; i < 2; i++) {
        int id = i * 256 + tid;
        int row = id >> 3, c = id & 7;
        koff[i] = (uint32_t)(row * FROW + c * 16);
        ksrc[i] = (size_t)row * Hd + c * 8;
        vsrc[i] = (size_t)row * Seq + c * 8;
    }

    // LDSM lane bases
    const uint32_t qBase = qpb +
        (uint32_t)((r0 + (lane & 15)) * FROW + (lane >> 4) * 16);
    const uint32_t kBase = st0 +
        (uint32_t)(((lane & 7) + ((lane >> 4) << 3)) * FROW +
                   (((lane >> 3) & 1) * 16));

    // ---- Prologue: Qhi + stage 0, then Qlo ----
    #pragma unroll
    for (int i = 0; i < 4; i++) {
        int id = i * 256 + tid;
        int row = id >> 3, c = id & 7;
        CP16(qpb + (uint32_t)(row * FROW + c * 16),
             g_qhi + bho + (size_t)(qt * 128 + row) * Hd + c * 8);
    }
    #pragma unroll
    for (int i = 0; i < 2; i++) {
        CP16(st0 + koff[i],              g_khi  + bho + ksrc[i]);
        CP16(st0 + KPLANE + koff[i],     g_klo  + bho + ksrc[i]);
        CP16(st0 + 2*KPLANE + koff[i],   g_vthi + bhv + vsrc[i]);
        CP16(st0 + 3*KPLANE + koff[i],   g_vtlo + bhv + vsrc[i]);
    }
    CP_COMMIT();
    CP_WAIT0();
    __syncthreads();

    uint32_t qhi[4][4], qlo[4][4];
    #pragma unroll
    for (int kk = 0; kk < 4; kk++) LDSM4(qhi[kk], qBase + kk * 32);
    __syncthreads();
    #pragma unroll
    for (int i = 0; i < 4; i++) {
        int id = i * 256 + tid;
        int row = id >> 3, c = id & 7;
        CP16(qpb + (uint32_t)(row * FROW + c * 16),
             g_qlo + bho + (size_t)(qt * 128 + row) * Hd + c * 8);
    }
    CP_COMMIT();
    CP_WAIT0();
    __syncthreads();
    #pragma unroll
    for (int kk = 0; kk < 4; kk++) LDSM4(qlo[kk], qBase + kk * 32);

    float m_i[2] = { -1e30f, -1e30f };
    float l_i[2] = { 0.f, 0.f };
    float oacc[8][4];
    #pragma unroll
    for (int ni = 0; ni < 8; ni++)
        #pragma unroll
        for (int j = 0; j < 4; j++) oacc[ni][j] = 0.f;

    const int jend = 2 * qt + 1;
    const int ig0  = qt * 128 + r0 + quad;

    for (int jt = 0; jt <= jend; jt++) {
        __syncthreads();

        const int cur = jt & 1;
        if (jt + 1 <= jend) {
            const uint32_t sb = st0 + (uint32_t)((jt + 1) & 1) * FSTGB;
            const size_t kro = (size_t)((jt + 1) * 64) * Hd;
            const size_t vro = (size_t)((jt + 1) * 64);
            #pragma unroll
            for (int i = 0; i < 2; i++) {
                CP16(sb + koff[i],              g_khi  + bho + kro + ksrc[i]);
                CP16(sb + KPLANE + koff[i],     g_klo  + bho + kro + ksrc[i]);
                CP16(sb + 2*KPLANE + koff[i],   g_vthi + bhv + vro + vsrc[i]);
                CP16(sb + 3*KPLANE + koff[i],   g_vtlo + bhv + vro + vsrc[i]);
            }
            CP_COMMIT();
            CP_WAIT1();
        } else {
            CP_WAIT0();
        }
        __syncthreads();

        // Causal skip: at the last KV tile, rows 0-63 (warps 0-3) are fully
        // masked -> contribute exactly zero; skip their compute entirely.
        if (jt == jend && wid < 4) continue;

        const uint32_t kB = kBase + (uint32_t)cur * FSTGB;
        const uint32_t vB = kB + 2 * KPLANE;

        // ---- S = Q K^T (3xBF16, LDSM B-frags) ----
        float sacc[8][4];
        #pragma unroll
        for (int ni = 0; ni < 8; ni++)
            #pragma unroll
            for (int j = 0; j < 4; j++) sacc[ni][j] = 0.f;

        #pragma unroll
        for (int p = 0; p < 4; p++) {
            #pragma unroll
            for (int kk = 0; kk < 4; kk++) {
                uint32_t kh[4], kl[4];
                LDSM4(kh, kB + p * (16 * FROW) + kk * 32);
                LDSM4(kl, kB + KPLANE + p * (16 * FROW) + kk * 32);
                mma_bf16_16x8x16(sacc[2*p],   qlo[kk], kh[0], kh[1]);
                mma_bf16_16x8x16(sacc[2*p],   qhi[kk], kl[0], kl[1]);
                mma_bf16_16x8x16(sacc[2*p],   qhi[kk], kh[0], kh[1]);
                mma_bf16_16x8x16(sacc[2*p+1], qlo[kk], kh[2], kh[3]);
                mma_bf16_16x8x16(sacc[2*p+1], qhi[kk], kl[2], kl[3]);
                mma_bf16_16x8x16(sacc[2*p+1], qhi[kk], kh[2], kh[3]);
            }
        }

        // ---- causal mask ----
        if (jt >= 2 * qt) {
            const int jg0 = jt * 64;
            #pragma unroll
            for (int ni = 0; ni < 8; ni++) {
                const int jg = jg0 + ni * 8 + 2 * tq;
                if (jg     > ig0)      sacc[ni][0] = -1e30f;
                if (jg + 1 > ig0)      sacc[ni][1] = -1e30f;
                if (jg     > ig0 + 8)  sacc[ni][2] = -1e30f;
                if (jg + 1 > ig0 + 8)  sacc[ni][3] = -1e30f;
            }
        }

        // ---- online softmax ----
        float mloc0 = -1e30f, mloc1 = -1e30f;
        #pragma unroll
        for (int ni = 0; ni < 8; ni++) {
            mloc0 = fmaxf(mloc0, fmaxf(sacc[ni][0], sacc[ni][1]));
            mloc1 = fmaxf(mloc1, fmaxf(sacc[ni][2], sacc[ni][3]));
        }
        #pragma unroll
        for (int off = 1; off < 4; off <<= 1) {
            mloc0 = fmaxf(mloc0, __shfl_xor_sync(0xffffffffu, mloc0, off));
            mloc1 = fmaxf(mloc1, __shfl_xor_sync(0xffffffffu, mloc1, off));
        }
        const float mnew0 = fmaxf(m_i[0], mloc0);
        const float mnew1 = fmaxf(m_i[1], mloc1);
        const float al0 = __expf(m_i[0] - mnew0);
        const float al1 = __expf(m_i[1] - mnew1);
        float ps0 = 0.f, ps1 = 0.f;
        #pragma unroll
        for (int ni = 0; ni < 8; ni++) {
            sacc[ni][0] = __expf(sacc[ni][0] - mnew0);
            sacc[ni][1] = __expf(sacc[ni][1] - mnew0);
            sacc[ni][2] = __expf(sacc[ni][2] - mnew1);
            sacc[ni][3] = __expf(sacc[ni][3] - mnew1);
            ps0 += sacc[ni][0] + sacc[ni][1];
            ps1 += sacc[ni][2] + sacc[ni][3];
        }
        #pragma unroll
        for (int off = 1; off < 4; off <<= 1) {
            ps0 += __shfl_xor_sync(0xffffffffu, ps0, off);
            ps1 += __shfl_xor_sync(0xffffffffu, ps1, off);
        }
        l_i[0] = l_i[0] * al0 + ps0;  m_i[0] = mnew0;
        l_i[1] = l_i[1] * al1 + ps1;  m_i[1] = mnew1;
        #pragma unroll
        for (int ni = 0; ni < 8; ni++) {
            oacc[ni][0] *= al0; oacc[ni][1] *= al0;
            oacc[ni][2] *= al1; oacc[ni][3] *= al1;
        }

        // ---- O += P V: P packed DIRECTLY from S C-fragments ----
        #pragma unroll
        for (int kk = 0; kk < 4; kk++) {
            uint32_t ph[4], pl[4];
            splitb(sacc[2*kk][0],   sacc[2*kk][1],   ph[0], pl[0]);
            splitb(sacc[2*kk][2],   sacc[2*kk][3],   ph[1], pl[1]);
            splitb(sacc[2*kk+1][0], sacc[2*kk+1][1], ph[2], pl[2]);
            splitb(sacc[2*kk+1][2], sacc[2*kk+1][3], ph[3], pl[3]);
            #pragma unroll
            for (int p = 0; p < 4; p++) {
                uint32_t vh[4], vl[4];
                LDSM4(vh, vB + p * (16 * FROW) + kk * 32);
                LDSM4(vl, vB + KPLANE + p * (16 * FROW) + kk * 32);
                mma_bf16_16x8x16(oacc[2*p],   pl, vh[0], vh[1]);
                mma_bf16_16x8x16(oacc[2*p],   ph, vl[0], vl[1]);
                mma_bf16_16x8x16(oacc[2*p],   ph, vh[0], vh[1]);
                mma_bf16_16x8x16(oacc[2*p+1], pl, vh[2], vh[3]);
                mma_bf16_16x8x16(oacc[2*p+1], ph, vl[2], vl[3]);
                mma_bf16_16x8x16(oacc[2*p+1], ph, vh[2], vh[3]);
            }
        }
    }

    // ---- normalize + write bf16 hi/lo att to [B,S,H,HD] ----
    const int bidx = bh >> 4, h = bh & 15;
    #pragma unroll
    for (int half = 0; half < 2; half++) {
        const float inv = 1.0f / l_i[half];
        const int s = qt * 128 + r0 + quad + half * 8;
        const size_t dof = ((size_t)bidx * Seq + s) * Hn * Hd + (size_t)h * Hd;
        #pragma unroll
        for (int ni = 0; ni < 8; ni++) {
            float vx = oacc[ni][half * 2 + 0] * inv;
            float vy = oacc[ni][half * 2 + 1] * inv;
            uint32_t hp, lp;
            splitb(vx, vy, hp, lp);
            *(uint32_t*)&g_ahi[dof + ni * 8 + 2 * tq] = hp;
            *(uint32_t*)&g_alo[dof + ni * 8 + 2 * tq] = lp;
        }
    }
}

// ---------------------------------------------------------------------------
extern "C" void kernel_launch(void* const* d_in, const int* in_sizes, int n_in,
                              void* d_out, int out_size)
{
    (void)in_sizes; (void)n_in; (void)out_size;
    const float* X    = (const float*)d_in[0];
    const float* Wq   = (const float*)d_in[1];
    const float* bq   = (const float*)d_in[2];
    const float* Wk   = (const float*)d_in[3];
    const float* bk   = (const float*)d_in[4];
    const float* Wv   = (const float*)d_in[5];
    const float* bv   = (const float*)d_in[6];
    const float* Wo   = (const float*)d_in[7];
    const float* bo   = (const float*)d_in[8];
    const float* comp = (const float*)d_in[9];
    float* out = (float*)d_out;

    cudaFuncSetAttribute(qkv_mma,   cudaFuncAttributeMaxDynamicSharedMemorySize, GEMM_SMEM_BYTES);
    cudaFuncSetAttribute(proj_mma,  cudaFuncAttributeMaxDynamicSharedMemorySize, GEMM_SMEM_BYTES);
    cudaFuncSetAttribute(flash_mma, cudaFuncAttributeMaxDynamicSharedMemorySize, FLASH_SMEM_BYTES);

    dim3 gS(512, 5);                     // split X + 4 W's
    split_xw<<<gS, 256>>>(X, Wq, Wk, Wv, Wo);

    dim3 gQKV(Dm/128, Mrows/128, 3);     // (8, 64, 3)
    qkv_mma<<<gQKV, 256, GEMM_SMEM_BYTES>>>(bq, bk, bv);

    dim3 gFA(Seq/128, Bsz*Hn);           // (16, 64)
    flash_mma<<<gFA, 256, FLASH_SMEM_BYTES>>>();

    dim3 gP(Dm/128, Mrows/128);          // (8, 64)
    proj_mma<<<gP, 256, GEMM_SMEM_BYTES>>>(bo, comp, out);
}